// round 15
// baseline (speedup 1.0000x reference)
#include <cuda_runtime.h>
#include <cuda_fp16.h>
#include <math.h>

#define Nn 20000
#define Ee 320000
#define Ll 16
#define Tt 64
#define Hh 128
#define Vv 32000
#define H3 384
#define NH (Nn*Hh)

// ---------------- scratch ----------------
__device__ float g_xw[NH];
__device__ float g_h1[NH];
__device__ float g_pos[NH];
__device__ float g_dinv[Nn];
__device__ int   g_cnt[Nn];
__device__ int   g_off[Nn + 1];
__device__ int   g_cur[Nn];
__device__ int   g_nbr[Ee];
__device__ int   g_dste[Ee];
__device__ int   g_eid[Ee];
__device__ float g_nrm[Ee];
__device__ __half g_E2h[Vv*H3];
__device__ float g_txt[NH];
__device__ __half g_preh[Nn*768];
__device__ unsigned g_w1p[2 * 3 * 64 * 128];

// ---------------- helpers ----------------
__device__ __forceinline__ float f2tf(float x) {
    unsigned u;
    asm("cvt.rna.tf32.f32 %0, %1;" : "=r"(u) : "f"(x));
    return __uint_as_float(u);
}
__device__ __forceinline__ unsigned pack_h2(float lo, float hi) {
    unsigned u;
    asm("cvt.rn.f16x2.f32 %0, %1, %2;" : "=r"(u) : "f"(hi), "f"(lo));
    return u;
}
__device__ __forceinline__ unsigned smem_addr(const void* p) {
    unsigned a;
    asm("{ .reg .u64 t; cvta.to.shared.u64 t, %1; cvt.u32.u64 %0, t; }" : "=r"(a) : "l"(p));
    return a;
}
__device__ __forceinline__ void cp_async16(unsigned saddr, const void* g) {
    asm volatile("cp.async.cg.shared.global [%0], [%1], 16;" :: "r"(saddr), "l"(g) : "memory");
}
#define CP_WAIT_ALL() asm volatile("cp.async.wait_all;" ::: "memory")

__device__ __forceinline__ void mma_tf32(float* d, const unsigned* a, const unsigned* b) {
    asm volatile(
        "mma.sync.aligned.m16n8k8.row.col.f32.tf32.tf32.f32 "
        "{%0,%1,%2,%3},{%4,%5,%6,%7},{%8,%9},{%0,%1,%2,%3};"
        : "+f"(d[0]), "+f"(d[1]), "+f"(d[2]), "+f"(d[3])
        : "r"(a[0]), "r"(a[1]), "r"(a[2]), "r"(a[3]), "r"(b[0]), "r"(b[1]));
}

__device__ __forceinline__ void mma_f16(float* d, const unsigned* a, const unsigned* b) {
    asm volatile(
        "mma.sync.aligned.m16n8k16.row.col.f32.f16.f16.f32 "
        "{%0,%1,%2,%3},{%4,%5,%6,%7},{%8,%9},{%0,%1,%2,%3};"
        : "+f"(d[0]), "+f"(d[1]), "+f"(d[2]), "+f"(d[3])
        : "r"(a[0]), "r"(a[1]), "r"(a[2]), "r"(a[3]), "r"(b[0]), "r"(b[1]));
}

// ---------------- CSR build ----------------
__global__ void k_hist(const int* __restrict__ dst, int* __restrict__ cnt) {
    int e = blockIdx.x * blockDim.x + threadIdx.x;
    if (e < Ee) atomicAdd(&cnt[dst[e]], 1);
}

__global__ void __launch_bounds__(1024) k_scan(const int* __restrict__ cnt,
                                               int* __restrict__ off,
                                               float* __restrict__ dinv) {
    __shared__ int part[1024];
    int t = threadIdx.x;
    int base = t * 20;
    int loc[20];
    int s = 0;
#pragma unroll
    for (int i = 0; i < 20; i++) {
        int idx = base + i;
        int v = (idx < Nn) ? cnt[idx] : 0;
        loc[i] = s;
        s += v;
        if (idx < Nn) dinv[idx] = rsqrtf((float)v + 1.0f);
    }
    part[t] = s;
    __syncthreads();
    for (int d = 1; d < 1024; d <<= 1) {
        int o = (t >= d) ? part[t - d] : 0;
        __syncthreads();
        part[t] += o;
        __syncthreads();
    }
    int pre = part[t] - s;
#pragma unroll
    for (int i = 0; i < 20; i++) {
        int idx = base + i;
        if (idx < Nn) off[idx] = pre + loc[i];
    }
    if (t == 1023) off[Nn] = Ee;
}

__global__ void k_fill(const int* __restrict__ src, const int* __restrict__ dst,
                       const float* __restrict__ dinv, const int* __restrict__ off,
                       int* __restrict__ cur, int* __restrict__ nbr,
                       int* __restrict__ dste, int* __restrict__ eid,
                       float* __restrict__ nrm) {
    int e = blockIdx.x * blockDim.x + threadIdx.x;
    if (e >= Ee) return;
    int s = src[e], d = dst[e];
    int p = atomicAdd(&cur[d], 1);
    int idx = off[d] + p;
    nbr[idx] = s;
    dste[idx] = d;
    eid[idx] = e;
    nrm[idx] = dinv[s] * dinv[d];
}

__global__ void __launch_bounds__(256) k_gather(
    const float* __restrict__ xw, const int* __restrict__ nbr,
    const float* __restrict__ nrm, const int* __restrict__ off,
    const float* __restrict__ dinv, const float* __restrict__ b,
    float* __restrict__ out) {
    int n = blockIdx.x * 2 + (threadIdx.x >> 7);
    int j = threadIdx.x & 127;
    int beg = off[n], end = off[n + 1];
    float acc = 0.f;
    for (int i = beg; i < end; i++) {
        int s = nbr[i];
        float wv = nrm[i];
        acc += xw[(size_t)s * 128 + j] * wv;
    }
    float di = dinv[n];
    float v = acc + xw[(size_t)n * 128 + j] * di * di + b[j];
    out[(size_t)n * 128 + j] = fmaxf(v, 0.f);
}

__global__ void k_xw1(const float* __restrict__ x, const float* __restrict__ w,
                      float* __restrict__ out) {
    int n = blockIdx.x;
    int h = threadIdx.x;
    __shared__ float xs[8];
    if (threadIdx.x < 8) xs[threadIdx.x] = x[n * 8 + threadIdx.x];
    __syncthreads();
    float s = 0.f;
#pragma unroll
    for (int f = 0; f < 8; f++) s += xs[f] * w[f * 128 + h];
    out[n * 128 + h] = s;
}

__global__ void k_packw(const float* __restrict__ rw1, const float* __restrict__ cw1,
                        unsigned* __restrict__ w1p) {
    int i = blockIdx.x * 256 + threadIdx.x;
    if (i >= 2 * 3 * 64 * 128) return;
    int head = i / 24576;
    int r = i % 24576;
    int c = r / 8192;
    int kp = (r >> 7) & 63;
    int n = r & 127;
    const float* W = head ? cw1 : rw1;
    int k = c * 128 + 2 * kp;
    w1p[i] = pack_h2(W[(size_t)k * 128 + n], W[(size_t)(k + 1) * 128 + n]);
}

// ---------------- fused 16-step GRU (proven) ----------------
#define GRU_SMEM ((384 * 64 + 32 * 64) * 4)
#define GSWZ(r, kw) ((r) * 64 + ((kw) ^ (((r) & 7) << 2)))

__global__ void __launch_bounds__(256, 2) k_gru_fused(
    const int* __restrict__ xtext, const __half* __restrict__ E2,
    const float* __restrict__ whh, const float* __restrict__ bih,
    const float* __restrict__ bhh, float* __restrict__ txt) {
    extern __shared__ unsigned gsm[];
    unsigned* Wsh = gsm;
    unsigned* hh = Wsh + 384 * 64;
    __shared__ int stok[32];
    __shared__ float sbih[384], sbhh[384];
    int tid = threadIdx.x;
    int w = tid >> 5, lane = tid & 31;
    int ly = lane >> 2, lx = lane & 3;
    int mt = w >> 2;
    int jq = w & 3;
    int m0 = blockIdx.x * 32;

    for (int i = tid; i < 384 * 32; i += 256) {
        int n = i >> 5;
        int kc4 = (i & 31) * 4;
        float4 v = *(const float4*)(whh + (size_t)n * 128 + kc4);
        int kw = kc4 >> 1;
        Wsh[GSWZ(n, kw)] = pack_h2(v.x, v.y);
        Wsh[GSWZ(n, kw + 1)] = pack_h2(v.z, v.w);
    }
    for (int i = tid; i < 32 * 64; i += 256) hh[i] = 0u;
    for (int i = tid; i < 384; i += 256) { sbih[i] = bih[i]; sbhh[i] = bhh[i]; }

    float tacc[4][4];
    float hreg[4][4];
#pragma unroll
    for (int u = 0; u < 4; u++)
#pragma unroll
        for (int p = 0; p < 4; p++) { tacc[u][p] = 0.f; hreg[u][p] = 0.f; }

    int row0 = mt * 16 + ly;
    __syncthreads();

    for (int step = 0; step < Ll; step++) {
        if (tid < 32) stok[tid] = xtext[(m0 + tid) * Ll + step];
        float acc[3][4][4];
#pragma unroll
        for (int g = 0; g < 3; g++)
#pragma unroll
            for (int u = 0; u < 4; u++)
#pragma unroll
                for (int p = 0; p < 4; p++) acc[g][u][p] = 0.f;

#pragma unroll
        for (int kc = 0; kc < 8; kc++) {
            int kw = kc * 8 + lx;
            unsigned a[4];
            a[0] = hh[GSWZ(row0, kw)];
            a[1] = hh[GSWZ(row0 + 8, kw)];
            a[2] = hh[GSWZ(row0, kw + 4)];
            a[3] = hh[GSWZ(row0 + 8, kw + 4)];
#pragma unroll
            for (int g = 0; g < 3; g++)
#pragma unroll
                for (int u = 0; u < 4; u++) {
                    int n = g * 128 + (jq * 4 + u) * 8 + ly;
                    unsigned b[2];
                    b[0] = Wsh[GSWZ(n, kw)];
                    b[1] = Wsh[GSWZ(n, kw + 4)];
                    mma_f16(acc[g][u], a, b);
                }
        }
        __syncthreads();

        int tok0 = stok[row0];
        int tok1 = stok[row0 + 8];
        const __half* e20 = E2 + (size_t)tok0 * H3;
        const __half* e21 = E2 + (size_t)tok1 * H3;
#pragma unroll
        for (int u = 0; u < 4; u++) {
            int j0 = (jq * 4 + u) * 8 + lx * 2;
            float bir0 = sbih[j0], bhr0 = sbhh[j0];
            float biz0 = sbih[128 + j0], bhz0 = sbhh[128 + j0];
            float bin0 = sbih[256 + j0], bhn0 = sbhh[256 + j0];
            float bir1 = sbih[j0 + 1], bhr1 = sbhh[j0 + 1];
            float biz1 = sbih[128 + j0 + 1], bhz1 = sbhh[128 + j0 + 1];
            float bin1 = sbih[256 + j0 + 1], bhn1 = sbhh[256 + j0 + 1];
            int kw = (jq * 4 + u) * 4 + lx;
#pragma unroll
            for (int rh = 0; rh < 2; rh++) {
                int r = row0 + rh * 8;
                const __half* e2 = rh ? e21 : e20;
                float h2v[2];
#pragma unroll
                for (int i = 0; i < 2; i++) {
                    int p = rh * 2 + i;
                    int j = j0 + i;
                    float gr = __half2float(e2[j]) + (i ? bir1 : bir0) + acc[0][u][p] + (i ? bhr1 : bhr0);
                    float gz = __half2float(e2[128 + j]) + (i ? biz1 : biz0) + acc[1][u][p] + (i ? bhz1 : bhz0);
                    float gn = __half2float(e2[256 + j]) + (i ? bin1 : bin0);
                    float hn = acc[2][u][p] + (i ? bhn1 : bhn0);
                    float rr = 1.f / (1.f + expf(-gr));
                    float zz = 1.f / (1.f + expf(-gz));
                    float nn_ = tanhf(gn + rr * hn);
                    float hp = hreg[u][p];
                    float h2 = (1.f - zz) * nn_ + zz * hp;
                    hreg[u][p] = h2;
                    tacc[u][p] += h2;
                    h2v[i] = h2;
                }
                hh[GSWZ(r, kw)] = pack_h2(h2v[0], h2v[1]);
            }
        }
        __syncthreads();
    }
#pragma unroll
    for (int u = 0; u < 4; u++)
#pragma unroll
        for (int p = 0; p < 4; p++) {
            int r = m0 + row0 + (p >> 1) * 8;
            int j = (jq * 4 + u) * 8 + lx * 2 + (p & 1);
            txt[(size_t)r * 128 + j] = tacc[u][p];
        }
}

// ---------------- generic tf32 GEMM (optional fp16 output) ----------------
template <bool NT, bool OUTH>
__global__ void __launch_bounds__(256) gemm_tf32(
    const float* __restrict__ A, int lda, const float* __restrict__ B, int ldb,
    void* __restrict__ Cv, int ldc, int M, int N, int K) {
    __shared__ float As[64 * 36];
    __shared__ float Bs[5120];
    int tid = threadIdx.x;
    int w = tid >> 5;
    int lane = tid & 31;
    int ly = lane >> 2, lx = lane & 3;
    int bm = blockIdx.x * 64, bn = blockIdx.y * 128;
    float acc[4][2][4];
#pragma unroll
    for (int i = 0; i < 4; i++)
#pragma unroll
        for (int j = 0; j < 2; j++)
#pragma unroll
            for (int q = 0; q < 4; q++) acc[i][j][q] = 0.f;

    for (int kt = 0; kt < K; kt += 32) {
#pragma unroll
        for (int l = 0; l < 2; l++) {
            int li = tid + l * 256;
            int row = li >> 3;
            int kc = (li & 7) * 4;
            float4 v = make_float4(0.f, 0.f, 0.f, 0.f);
            if (bm + row < M) v = *(const float4*)(A + (size_t)(bm + row) * lda + kt + kc);
            float4 t;
            t.x = f2tf(v.x); t.y = f2tf(v.y); t.z = f2tf(v.z); t.w = f2tf(v.w);
            *(float4*)&As[row * 36 + kc] = t;
        }
        if (NT) {
#pragma unroll
            for (int l = 0; l < 4; l++) {
                int li = tid + l * 256;
                int n = li >> 3;
                int kc = (li & 7) * 4;
                float4 v = *(const float4*)(B + (size_t)(bn + n) * ldb + kt + kc);
                float4 t;
                t.x = f2tf(v.x); t.y = f2tf(v.y); t.z = f2tf(v.z); t.w = f2tf(v.w);
                *(float4*)&Bs[n * 40 + kc] = t;
            }
        } else {
#pragma unroll
            for (int l = 0; l < 4; l++) {
                int li = tid + l * 256;
                int k = li >> 5;
                int nc = (li & 31) * 4;
                float4 v = *(const float4*)(B + (size_t)(kt + k) * ldb + bn + nc);
                float4 t;
                t.x = f2tf(v.x); t.y = f2tf(v.y); t.z = f2tf(v.z); t.w = f2tf(v.w);
                *(float4*)&Bs[k * 136 + nc] = t;
            }
        }
        __syncthreads();
#pragma unroll
        for (int kk = 0; kk < 4; kk++) {
            unsigned a[4][4];
#pragma unroll
            for (int mt = 0; mt < 4; mt++) {
                int row = mt * 16 + ly;
                int k = kk * 8 + lx;
                a[mt][0] = __float_as_uint(As[row * 36 + k]);
                a[mt][1] = __float_as_uint(As[(row + 8) * 36 + k]);
                a[mt][2] = __float_as_uint(As[row * 36 + k + 4]);
                a[mt][3] = __float_as_uint(As[(row + 8) * 36 + k + 4]);
            }
            unsigned b[2][2];
#pragma unroll
            for (int nt = 0; nt < 2; nt++) {
                int n = w * 16 + nt * 8 + ly;
                int k = kk * 8 + lx;
                if (NT) {
                    b[nt][0] = __float_as_uint(Bs[n * 40 + k]);
                    b[nt][1] = __float_as_uint(Bs[n * 40 + k + 4]);
                } else {
                    b[nt][0] = __float_as_uint(Bs[k * 136 + n]);
                    b[nt][1] = __float_as_uint(Bs[(k + 4) * 136 + n]);
                }
            }
#pragma unroll
            for (int mt = 0; mt < 4; mt++)
#pragma unroll
                for (int nt = 0; nt < 2; nt++) mma_tf32(acc[mt][nt], a[mt], b[nt]);
        }
        __syncthreads();
    }
#pragma unroll
    for (int mt = 0; mt < 4; mt++)
#pragma unroll
        for (int nt = 0; nt < 2; nt++) {
            int row = bm + mt * 16 + ly;
            int col = bn + w * 16 + nt * 8 + lx * 2;
            if (OUTH) {
                __half* C = (__half*)Cv;
                if (row < M)
                    *(__half2*)(C + (size_t)row * ldc + col) =
                        __floats2half2_rn(acc[mt][nt][0], acc[mt][nt][1]);
                if (row + 8 < M)
                    *(__half2*)(C + (size_t)(row + 8) * ldc + col) =
                        __floats2half2_rn(acc[mt][nt][2], acc[mt][nt][3]);
            } else {
                float* C = (float*)Cv;
                if (row < M) {
                    C[(size_t)row * ldc + col] = acc[mt][nt][0];
                    C[(size_t)row * ldc + col + 1] = acc[mt][nt][1];
                }
                if (row + 8 < M) {
                    C[(size_t)(row + 8) * ldc + col] = acc[mt][nt][2];
                    C[(size_t)(row + 8) * ldc + col + 1] = acc[mt][nt][3];
                }
            }
        }
}

// ---------------- dual-B NN GEMM, fp16 output ----------------
__global__ void __launch_bounds__(256) gemm_tf32_dual(
    const float* __restrict__ A, int lda, const float* __restrict__ B1,
    const float* __restrict__ B2, int ldb, __half* __restrict__ C, int ldc,
    int M, int K) {
    const float* B = blockIdx.y ? B2 : B1;
    int cb = blockIdx.y * 128;
    __shared__ float As[64 * 36];
    __shared__ float Bs[5120];
    int tid = threadIdx.x;
    int w = tid >> 5;
    int lane = tid & 31;
    int ly = lane >> 2, lx = lane & 3;
    int bm = blockIdx.x * 64;
    float acc[4][2][4];
#pragma unroll
    for (int i = 0; i < 4; i++)
#pragma unroll
        for (int j = 0; j < 2; j++)
#pragma unroll
            for (int q = 0; q < 4; q++) acc[i][j][q] = 0.f;

    for (int kt = 0; kt < K; kt += 32) {
#pragma unroll
        for (int l = 0; l < 2; l++) {
            int li = tid + l * 256;
            int row = li >> 3;
            int kc = (li & 7) * 4;
            float4 v = make_float4(0.f, 0.f, 0.f, 0.f);
            if (bm + row < M) v = *(const float4*)(A + (size_t)(bm + row) * lda + kt + kc);
            float4 t;
            t.x = f2tf(v.x); t.y = f2tf(v.y); t.z = f2tf(v.z); t.w = f2tf(v.w);
            *(float4*)&As[row * 36 + kc] = t;
        }
#pragma unroll
        for (int l = 0; l < 4; l++) {
            int li = tid + l * 256;
            int k = li >> 5;
            int nc = (li & 31) * 4;
            float4 v = *(const float4*)(B + (size_t)(kt + k) * ldb + nc);
            float4 t;
            t.x = f2tf(v.x); t.y = f2tf(v.y); t.z = f2tf(v.z); t.w = f2tf(v.w);
            *(float4*)&Bs[k * 136 + nc] = t;
        }
        __syncthreads();
#pragma unroll
        for (int kk = 0; kk < 4; kk++) {
            unsigned a[4][4];
#pragma unroll
            for (int mt = 0; mt < 4; mt++) {
                int row = mt * 16 + ly;
                int k = kk * 8 + lx;
                a[mt][0] = __float_as_uint(As[row * 36 + k]);
                a[mt][1] = __float_as_uint(As[(row + 8) * 36 + k]);
                a[mt][2] = __float_as_uint(As[row * 36 + k + 4]);
                a[mt][3] = __float_as_uint(As[(row + 8) * 36 + k + 4]);
            }
            unsigned b[2][2];
#pragma unroll
            for (int nt = 0; nt < 2; nt++) {
                int n = w * 16 + nt * 8 + ly;
                int k = kk * 8 + lx;
                b[nt][0] = __float_as_uint(Bs[k * 136 + n]);
                b[nt][1] = __float_as_uint(Bs[(k + 4) * 136 + n]);
            }
#pragma unroll
            for (int mt = 0; mt < 4; mt++)
#pragma unroll
                for (int nt = 0; nt < 2; nt++) mma_tf32(acc[mt][nt], a[mt], b[nt]);
        }
        __syncthreads();
    }
#pragma unroll
    for (int mt = 0; mt < 4; mt++)
#pragma unroll
        for (int nt = 0; nt < 2; nt++) {
            int row = bm + mt * 16 + ly;
            int col = cb + w * 16 + nt * 8 + lx * 2;
            if (row < M)
                *(__half2*)(C + (size_t)row * ldc + col) =
                    __floats2half2_rn(acc[mt][nt][0], acc[mt][nt][1]);
            if (row + 8 < M)
                *(__half2*)(C + (size_t)(row + 8) * ldc + col) =
                    __floats2half2_rn(acc[mt][nt][2], acc[mt][nt][3]);
        }
}

// ---------------- fused edge heads (CSR-ordered edges + cp.async W prefetch) ----------------
#define EH_ASW  (64 * 68)
#define EH_WPW  (64 * 136)
#define EH_SMEM ((EH_ASW + 2 * EH_WPW + 1024) * 4)

__global__ void __launch_bounds__(256, 2) k_edge_heads_f16(
    const int* __restrict__ nbr, const int* __restrict__ dste,
    const int* __restrict__ eid,
    const __half* __restrict__ pre, const unsigned* __restrict__ w1p,
    const float* __restrict__ bpos, const float* __restrict__ btxt,
    const float* __restrict__ bimg,
    const float* __restrict__ rb1, const float* __restrict__ rw2,
    const float* __restrict__ rb2,
    const float* __restrict__ cb1, const float* __restrict__ cw2,
    const float* __restrict__ cb2,
    float* __restrict__ out) {
    extern __shared__ unsigned shm[];
    unsigned* Asw = shm;
    unsigned* Wrp = Asw + EH_ASW;
    unsigned* Wcp = Wrp + EH_WPW;
    float* red = (float*)(Wcp + EH_WPW);
    __shared__ int ssrc[64];
    __shared__ int sdst[64];
    __shared__ int seid[64];
    __shared__ float sbias[384];
    int tid = threadIdx.x;
    int w = tid >> 5;
    int lane = tid & 31;
    int ly = lane >> 2, lx = lane & 3;
    int head = w & 1;
    int q = w >> 1;
    int n0 = q * 32;
    int e0 = blockIdx.x * 64;
    if (tid < 64) {
        ssrc[tid] = nbr[e0 + tid];
        sdst[tid] = dste[e0 + tid];
        seid[tid] = eid[e0 + tid];
    }
    for (int i = tid; i < 384; i += 256) {
        int region = i >> 7, j = i & 127;
        const float* bsrc = (region == 0) ? bpos : ((region == 1) ? btxt : bimg);
        sbias[i] = bsrc[j];
    }

    float acc[4][4][4];
#pragma unroll
    for (int i = 0; i < 4; i++)
#pragma unroll
        for (int j = 0; j < 4; j++)
#pragma unroll
            for (int p = 0; p < 4; p++) acc[i][j][p] = 0.f;

    for (int c = 0; c < 3; c++) {
        __syncthreads();
        // prefetch W chunks (both heads) via cp.async
        {
            const unsigned* WgR = w1p + (size_t)c * 8192;
            const unsigned* WgC = w1p + (size_t)(3 + c) * 8192;
#pragma unroll
            for (int l = 0; l < 8; l++) {
                int idx = tid + l * 256;
                int kp = idx >> 5;
                int n4 = (idx & 31) * 4;
                cp_async16(smem_addr(&Wrp[kp * 136 + n4]), WgR + kp * 128 + n4);
                cp_async16(smem_addr(&Wcp[kp * 136 + n4]), WgC + kp * 128 + n4);
            }
        }
        // A tile: 64 CSR-ordered edges; dst rows highly L1-coherent
#pragma unroll
        for (int l = 0; l < 16; l++) {
            int idx2 = tid + l * 256;
            int m = idx2 >> 6;
            int k2 = (idx2 & 63) * 2;
            int s = ssrc[m], d = sdst[m];
            float2 va = __half22float2(*(const __half2*)(pre + (size_t)s * 768 + c * 256 + k2));
            float2 vb = __half22float2(*(const __half2*)(pre + (size_t)d * 768 + c * 256 + 128 + k2));
            float xx = fmaxf(va.x + vb.x + sbias[c * 128 + k2], 0.f);
            float yy = fmaxf(va.y + vb.y + sbias[c * 128 + k2 + 1], 0.f);
            Asw[m * 68 + (k2 >> 1)] = pack_h2(xx, yy);
        }
        CP_WAIT_ALL();
        __syncthreads();
        const unsigned* Wp = head ? Wcp : Wrp;
#pragma unroll
        for (int kk = 0; kk < 8; kk++) {
            int kp = kk * 8 + lx;
            unsigned b[4][2];
#pragma unroll
            for (int nt = 0; nt < 4; nt++) {
                int n = n0 + nt * 8 + ly;
                b[nt][0] = Wp[kp * 136 + n];
                b[nt][1] = Wp[(kp + 4) * 136 + n];
            }
#pragma unroll
            for (int mt = 0; mt < 4; mt++) {
                int wbase = (mt * 16 + ly) * 68 + kk * 8 + lx;
                unsigned a[4];
                a[0] = Asw[wbase];
                a[1] = Asw[wbase + 8 * 68];
                a[2] = Asw[wbase + 4];
                a[3] = Asw[wbase + 8 * 68 + 4];
#pragma unroll
                for (int nt = 0; nt < 4; nt++) mma_f16(acc[mt][nt], a, b[nt]);
            }
        }
    }

    const float* b1 = head ? cb1 : rb1;
    const float* w2 = head ? cw2 : rw2;
    float p[4][2][2];
#pragma unroll
    for (int mt = 0; mt < 4; mt++)
#pragma unroll
        for (int rr = 0; rr < 2; rr++) { p[mt][rr][0] = 0.f; p[mt][rr][1] = 0.f; }
#pragma unroll
    for (int nt = 0; nt < 4; nt++) {
        int j0 = n0 + nt * 8 + lx * 2;
        float b10 = b1[j0], b11 = b1[j0 + 1];
        float w200 = w2[j0 * 2], w201 = w2[j0 * 2 + 1];
        float w210 = w2[(j0 + 1) * 2], w211 = w2[(j0 + 1) * 2 + 1];
#pragma unroll
        for (int mt = 0; mt < 4; mt++) {
            float h0 = fmaxf(acc[mt][nt][0] + b10, 0.f);
            float h1 = fmaxf(acc[mt][nt][1] + b11, 0.f);
            float h2 = fmaxf(acc[mt][nt][2] + b10, 0.f);
            float h3 = fmaxf(acc[mt][nt][3] + b11, 0.f);
            p[mt][0][0] += h0 * w200 + h1 * w210;
            p[mt][0][1] += h0 * w201 + h1 * w211;
            p[mt][1][0] += h2 * w200 + h3 * w210;
            p[mt][1][1] += h2 * w201 + h3 * w211;
        }
    }
#pragma unroll
    for (int mt = 0; mt < 4; mt++)
#pragma unroll
        for (int rr = 0; rr < 2; rr++)
#pragma unroll
            for (int cl = 0; cl < 2; cl++) {
                float v = p[mt][rr][cl];
                v += __shfl_down_sync(0xffffffffu, v, 2, 4);
                v += __shfl_down_sync(0xffffffffu, v, 1, 4);
                p[mt][rr][cl] = v;
            }
    if (lx == 0) {
#pragma unroll
        for (int mt = 0; mt < 4; mt++)
#pragma unroll
            for (int rr = 0; rr < 2; rr++) {
                int row = mt * 16 + ly + rr * 8;
                red[((head * 4 + q) * 64 + row) * 2 + 0] = p[mt][rr][0];
                red[((head * 4 + q) * 64 + row) * 2 + 1] = p[mt][rr][1];
            }
    }
    __syncthreads();
    if (tid < 128) {
        int m = tid & 63;
        int h = tid >> 6;
        float l0 = 0.f, l1 = 0.f;
#pragma unroll
        for (int qq = 0; qq < 4; qq++) {
            l0 += red[((h * 4 + qq) * 64 + m) * 2 + 0];
            l1 += red[((h * 4 + qq) * 64 + m) * 2 + 1];
        }
        const float* b2 = h ? cb2 : rb2;
        l0 += b2[0];
        l1 += b2[1];
        float mx = fmaxf(l0, l1);
        float lse = mx + logf(expf(l0 - mx) + expf(l1 - mx));
        size_t base = ((size_t)h * Ee + seid[m]) * 2;
        out[base + 0] = l0 - lse;
        out[base + 1] = l1 - lse;
    }
}

// ---------------- launch ----------------
extern "C" void kernel_launch(void* const* d_in, const int* in_sizes, int n_in,
                              void* d_out, int out_size) {
    const float* x     = (const float*)d_in[0];
    const int*   ei    = (const int*)d_in[1];
    const int*   xtext = (const int*)d_in[2];
    const float* img   = (const float*)d_in[3];
    const float* c1w   = (const float*)d_in[4];
    const float* c1b   = (const float*)d_in[5];
    const float* c2w   = (const float*)d_in[6];
    const float* c2b   = (const float*)d_in[7];
    const float* emb   = (const float*)d_in[8];
    const float* wih   = (const float*)d_in[9];
    const float* whh   = (const float*)d_in[10];
    const float* bih   = (const float*)d_in[11];
    const float* bhh   = (const float*)d_in[12];
    const float* lpw   = (const float*)d_in[13];
    const float* lpb   = (const float*)d_in[14];
    const float* ltw   = (const float*)d_in[15];
    const float* ltb   = (const float*)d_in[16];
    const float* liw   = (const float*)d_in[17];
    const float* lib   = (const float*)d_in[18];
    const float* rw1   = (const float*)d_in[19];
    const float* rb1   = (const float*)d_in[20];
    const float* rw2   = (const float*)d_in[21];
    const float* rb2   = (const float*)d_in[22];
    const float* cw1   = (const float*)d_in[23];
    const float* cb1   = (const float*)d_in[24];
    const float* cw2   = (const float*)d_in[25];
    const float* cb2   = (const float*)d_in[26];
    float* out = (float*)d_out;
    const int* srcp = ei;
    const int* dstp = ei + Ee;

    float *p_xw, *p_h1, *p_pos, *p_dinv, *p_txt, *p_nrm;
    __half *p_E2h, *p_preh;
    unsigned* p_w1p;
    int *p_cnt, *p_off, *p_cur, *p_nbr, *p_dste, *p_eid;
    cudaGetSymbolAddress((void**)&p_xw, g_xw);
    cudaGetSymbolAddress((void**)&p_h1, g_h1);
    cudaGetSymbolAddress((void**)&p_pos, g_pos);
    cudaGetSymbolAddress((void**)&p_dinv, g_dinv);
    cudaGetSymbolAddress((void**)&p_cnt, g_cnt);
    cudaGetSymbolAddress((void**)&p_off, g_off);
    cudaGetSymbolAddress((void**)&p_cur, g_cur);
    cudaGetSymbolAddress((void**)&p_nbr, g_nbr);
    cudaGetSymbolAddress((void**)&p_dste, g_dste);
    cudaGetSymbolAddress((void**)&p_eid, g_eid);
    cudaGetSymbolAddress((void**)&p_nrm, g_nrm);
    cudaGetSymbolAddress((void**)&p_E2h, g_E2h);
    cudaGetSymbolAddress((void**)&p_txt, g_txt);
    cudaGetSymbolAddress((void**)&p_preh, g_preh);
    cudaGetSymbolAddress((void**)&p_w1p, g_w1p);

    static cudaStream_t sB = 0, sC = 0;
    static cudaEvent_t ev0 = 0, evB = 0, evC = 0, evX = 0;
    if (!sB) {
        cudaStreamCreateWithFlags(&sB, cudaStreamNonBlocking);
        cudaStreamCreateWithFlags(&sC, cudaStreamNonBlocking);
        cudaEventCreateWithFlags(&ev0, cudaEventDisableTiming);
        cudaEventCreateWithFlags(&evB, cudaEventDisableTiming);
        cudaEventCreateWithFlags(&evC, cudaEventDisableTiming);
        cudaEventCreateWithFlags(&evX, cudaEventDisableTiming);
        cudaFuncSetAttribute(k_gru_fused, cudaFuncAttributeMaxDynamicSharedMemorySize, GRU_SMEM);
        cudaFuncSetAttribute(k_edge_heads_f16, cudaFuncAttributeMaxDynamicSharedMemorySize, EH_SMEM);
    }

    // fork
    cudaEventRecord(ev0, 0);
    cudaStreamWaitEvent(sB, ev0, 0);
    cudaStreamWaitEvent(sC, ev0, 0);

    // ---- stream B: text chain ----
    {
        dim3 g((Vv + 63) / 64, H3 / 128);
        gemm_tf32<true, true><<<g, 256, 0, sB>>>(emb, Tt, wih, Tt, p_E2h, H3, Vv, H3, Tt);
        k_gru_fused<<<Nn / 32, 256, GRU_SMEM, sB>>>(xtext, p_E2h, whh, bih, bhh, p_txt);
        dim3 gd((Nn + 63) / 64, 2);
        gemm_tf32_dual<<<gd, 256, 0, sB>>>(p_txt, 128, ltw, ltw + 128 * 128, 128,
                                           p_preh + 256, 768, Nn, 128);
        cudaEventRecord(evB, sB);
    }

    // ---- stream C: xw1, W1 pack, img pre pair ----
    {
        k_xw1<<<Nn, 128, 0, sC>>>(x, c1w, p_xw);
        cudaEventRecord(evX, sC);
        k_packw<<<(2 * 3 * 64 * 128 + 255) / 256, 256, 0, sC>>>(rw1, cw1, p_w1p);
        dim3 gd((Nn + 63) / 64, 2);
        gemm_tf32_dual<<<gd, 256, 0, sC>>>(img, 256, liw, liw + 256 * 128, 128,
                                           p_preh + 512, 768, Nn, 256);
        cudaEventRecord(evC, sC);
    }

    // ---- default stream: CSR build || xw1, GCN gathers, pos pre pair ----
    cudaMemsetAsync(p_cnt, 0, Nn * sizeof(int));
    cudaMemsetAsync(p_cur, 0, Nn * sizeof(int));
    k_hist<<<(Ee + 255) / 256, 256>>>(dstp, p_cnt);
    k_scan<<<1, 1024>>>(p_cnt, p_off, p_dinv);
    k_fill<<<(Ee + 255) / 256, 256>>>(srcp, dstp, p_dinv, p_off, p_cur,
                                      p_nbr, p_dste, p_eid, p_nrm);

    cudaStreamWaitEvent(0, evX, 0);
    k_gather<<<Nn / 2, 256>>>(p_xw, p_nbr, p_nrm, p_off, p_dinv, c1b, p_h1);

    {
        dim3 g((Nn + 63) / 64, 1);
        gemm_tf32<false, false><<<g, 256>>>(p_h1, 128, c2w, 128, p_xw, 128, Nn, 128, 128);
    }
    k_gather<<<Nn / 2, 256>>>(p_xw, p_nbr, p_nrm, p_off, p_dinv, c2b, p_pos);

    {
        dim3 gd((Nn + 63) / 64, 2);
        gemm_tf32_dual<<<gd, 256>>>(p_pos, 128, lpw, lpw + 128 * 128, 128,
                                    p_preh + 0, 768, Nn, 128);
    }

    // join
    cudaStreamWaitEvent(0, evB, 0);
    cudaStreamWaitEvent(0, evC, 0);

    // fused edge heads over CSR-ordered edges
    k_edge_heads_f16<<<Ee / 64, 256, EH_SMEM>>>(p_nbr, p_dste, p_eid, p_preh, p_w1p,
                                                lpb, ltb, lib,
                                                rb1, rw2, rb2, cb1, cw2, cb2, out);
    (void)in_sizes; (void)n_in; (void)out_size;
}

// round 16
// speedup vs baseline: 1.0345x; 1.0345x over previous
#include <cuda_runtime.h>
#include <cuda_fp16.h>
#include <math.h>

#define Nn 20000
#define Ee 320000
#define Ll 16
#define Tt 64
#define Hh 128
#define Vv 32000
#define H3 384
#define NH (Nn*Hh)

// ---------------- scratch ----------------
__device__ float g_xw[NH];
__device__ float g_h1[NH];
__device__ float g_pos[NH];
__device__ float g_dinv[Nn];
__device__ int   g_cnt[Nn];
__device__ int   g_off[Nn + 1];
__device__ int   g_cur[Nn];
__device__ int   g_nbr[Ee];
__device__ float g_nrm[Ee];
__device__ __half g_E2h[Vv*H3];
__device__ float g_txt[NH];
__device__ __half g_preh[Nn*768];
__device__ unsigned g_w1p[2 * 3 * 64 * 128];

// ---------------- helpers ----------------
__device__ __forceinline__ float f2tf(float x) {
    unsigned u;
    asm("cvt.rna.tf32.f32 %0, %1;" : "=r"(u) : "f"(x));
    return __uint_as_float(u);
}
__device__ __forceinline__ unsigned pack_h2(float lo, float hi) {
    unsigned u;
    asm("cvt.rn.f16x2.f32 %0, %1, %2;" : "=r"(u) : "f"(hi), "f"(lo));
    return u;
}
__device__ __forceinline__ unsigned smem_addr(const void* p) {
    unsigned a;
    asm("{ .reg .u64 t; cvta.to.shared.u64 t, %1; cvt.u32.u64 %0, t; }" : "=r"(a) : "l"(p));
    return a;
}
__device__ __forceinline__ void cp_async16(unsigned saddr, const void* g) {
    asm volatile("cp.async.cg.shared.global [%0], [%1], 16;" :: "r"(saddr), "l"(g) : "memory");
}
#define CP_WAIT_ALL() asm volatile("cp.async.wait_all;" ::: "memory")

__device__ __forceinline__ void mma_tf32(float* d, const unsigned* a, const unsigned* b) {
    asm volatile(
        "mma.sync.aligned.m16n8k8.row.col.f32.tf32.tf32.f32 "
        "{%0,%1,%2,%3},{%4,%5,%6,%7},{%8,%9},{%0,%1,%2,%3};"
        : "+f"(d[0]), "+f"(d[1]), "+f"(d[2]), "+f"(d[3])
        : "r"(a[0]), "r"(a[1]), "r"(a[2]), "r"(a[3]), "r"(b[0]), "r"(b[1]));
}

__device__ __forceinline__ void mma_f16(float* d, const unsigned* a, const unsigned* b) {
    asm volatile(
        "mma.sync.aligned.m16n8k16.row.col.f32.f16.f16.f32 "
        "{%0,%1,%2,%3},{%4,%5,%6,%7},{%8,%9},{%0,%1,%2,%3};"
        : "+f"(d[0]), "+f"(d[1]), "+f"(d[2]), "+f"(d[3])
        : "r"(a[0]), "r"(a[1]), "r"(a[2]), "r"(a[3]), "r"(b[0]), "r"(b[1]));
}

// ---------------- CSR build ----------------
__global__ void k_hist(const int* __restrict__ dst, int* __restrict__ cnt) {
    int e = blockIdx.x * blockDim.x + threadIdx.x;
    if (e < Ee) atomicAdd(&cnt[dst[e]], 1);
}

__global__ void __launch_bounds__(1024) k_scan(const int* __restrict__ cnt,
                                               int* __restrict__ off,
                                               float* __restrict__ dinv) {
    __shared__ int part[1024];
    int t = threadIdx.x;
    int base = t * 20;
    int loc[20];
    int s = 0;
#pragma unroll
    for (int i = 0; i < 20; i++) {
        int idx = base + i;
        int v = (idx < Nn) ? cnt[idx] : 0;
        loc[i] = s;
        s += v;
        if (idx < Nn) dinv[idx] = rsqrtf((float)v + 1.0f);
    }
    part[t] = s;
    __syncthreads();
    for (int d = 1; d < 1024; d <<= 1) {
        int o = (t >= d) ? part[t - d] : 0;
        __syncthreads();
        part[t] += o;
        __syncthreads();
    }
    int pre = part[t] - s;
#pragma unroll
    for (int i = 0; i < 20; i++) {
        int idx = base + i;
        if (idx < Nn) off[idx] = pre + loc[i];
    }
    if (t == 1023) off[Nn] = Ee;
}

__global__ void k_fill(const int* __restrict__ src, const int* __restrict__ dst,
                       const float* __restrict__ dinv, const int* __restrict__ off,
                       int* __restrict__ cur, int* __restrict__ nbr,
                       float* __restrict__ nrm) {
    int e = blockIdx.x * blockDim.x + threadIdx.x;
    if (e >= Ee) return;
    int s = src[e], d = dst[e];
    int p = atomicAdd(&cur[d], 1);
    int idx = off[d] + p;
    nbr[idx] = s;
    nrm[idx] = dinv[s] * dinv[d];
}

// gather: 8 nodes/block, 32 threads/node, float4 loads, unroll x2
__global__ void __launch_bounds__(256) k_gather(
    const float* __restrict__ xw, const int* __restrict__ nbr,
    const float* __restrict__ nrm, const int* __restrict__ off,
    const float* __restrict__ dinv, const float* __restrict__ b,
    float* __restrict__ out) {
    int n = blockIdx.x * 8 + (threadIdx.x >> 5);
    int j4 = threadIdx.x & 31;           // float4 column 0..31
    const float4* xw4 = (const float4*)xw;
    int beg = off[n], end = off[n + 1];
    float4 acc = make_float4(0.f, 0.f, 0.f, 0.f);
    int i = beg;
    for (; i + 2 <= end; i += 2) {
        int s0 = nbr[i], s1 = nbr[i + 1];
        float w0 = nrm[i], w1 = nrm[i + 1];
        float4 v0 = xw4[(size_t)s0 * 32 + j4];
        float4 v1 = xw4[(size_t)s1 * 32 + j4];
        acc.x += v0.x * w0 + v1.x * w1;
        acc.y += v0.y * w0 + v1.y * w1;
        acc.z += v0.z * w0 + v1.z * w1;
        acc.w += v0.w * w0 + v1.w * w1;
    }
    if (i < end) {
        int s0 = nbr[i];
        float w0 = nrm[i];
        float4 v0 = xw4[(size_t)s0 * 32 + j4];
        acc.x += v0.x * w0;
        acc.y += v0.y * w0;
        acc.z += v0.z * w0;
        acc.w += v0.w * w0;
    }
    float di = dinv[n];
    float sc = di * di;
    float4 self = xw4[(size_t)n * 32 + j4];
    float4 bb = *(const float4*)(b + j4 * 4);
    float4 o;
    o.x = fmaxf(acc.x + self.x * sc + bb.x, 0.f);
    o.y = fmaxf(acc.y + self.y * sc + bb.y, 0.f);
    o.z = fmaxf(acc.z + self.z * sc + bb.z, 0.f);
    o.w = fmaxf(acc.w + self.w * sc + bb.w, 0.f);
    ((float4*)out)[(size_t)n * 32 + j4] = o;
}

__global__ void k_xw1(const float* __restrict__ x, const float* __restrict__ w,
                      float* __restrict__ out) {
    int n = blockIdx.x;
    int h = threadIdx.x;
    __shared__ float xs[8];
    if (threadIdx.x < 8) xs[threadIdx.x] = x[n * 8 + threadIdx.x];
    __syncthreads();
    float s = 0.f;
#pragma unroll
    for (int f = 0; f < 8; f++) s += xs[f] * w[f * 128 + h];
    out[n * 128 + h] = s;
}

__global__ void k_packw(const float* __restrict__ rw1, const float* __restrict__ cw1,
                        unsigned* __restrict__ w1p) {
    int i = blockIdx.x * 256 + threadIdx.x;
    if (i >= 2 * 3 * 64 * 128) return;
    int head = i / 24576;
    int r = i % 24576;
    int c = r / 8192;
    int kp = (r >> 7) & 63;
    int n = r & 127;
    const float* W = head ? cw1 : rw1;
    int k = c * 128 + 2 * kp;
    w1p[i] = pack_h2(W[(size_t)k * 128 + n], W[(size_t)(k + 1) * 128 + n]);
}

// ---------------- fused 16-step GRU (proven) ----------------
#define GRU_SMEM ((384 * 64 + 32 * 64) * 4)
#define GSWZ(r, kw) ((r) * 64 + ((kw) ^ (((r) & 7) << 2)))

__global__ void __launch_bounds__(256, 2) k_gru_fused(
    const int* __restrict__ xtext, const __half* __restrict__ E2,
    const float* __restrict__ whh, const float* __restrict__ bih,
    const float* __restrict__ bhh, float* __restrict__ txt) {
    extern __shared__ unsigned gsm[];
    unsigned* Wsh = gsm;
    unsigned* hh = Wsh + 384 * 64;
    __shared__ int stok[32];
    __shared__ float sbih[384], sbhh[384];
    int tid = threadIdx.x;
    int w = tid >> 5, lane = tid & 31;
    int ly = lane >> 2, lx = lane & 3;
    int mt = w >> 2;
    int jq = w & 3;
    int m0 = blockIdx.x * 32;

    for (int i = tid; i < 384 * 32; i += 256) {
        int n = i >> 5;
        int kc4 = (i & 31) * 4;
        float4 v = *(const float4*)(whh + (size_t)n * 128 + kc4);
        int kw = kc4 >> 1;
        Wsh[GSWZ(n, kw)] = pack_h2(v.x, v.y);
        Wsh[GSWZ(n, kw + 1)] = pack_h2(v.z, v.w);
    }
    for (int i = tid; i < 32 * 64; i += 256) hh[i] = 0u;
    for (int i = tid; i < 384; i += 256) { sbih[i] = bih[i]; sbhh[i] = bhh[i]; }

    float tacc[4][4];
    float hreg[4][4];
#pragma unroll
    for (int u = 0; u < 4; u++)
#pragma unroll
        for (int p = 0; p < 4; p++) { tacc[u][p] = 0.f; hreg[u][p] = 0.f; }

    int row0 = mt * 16 + ly;
    __syncthreads();

    for (int step = 0; step < Ll; step++) {
        if (tid < 32) stok[tid] = xtext[(m0 + tid) * Ll + step];
        float acc[3][4][4];
#pragma unroll
        for (int g = 0; g < 3; g++)
#pragma unroll
            for (int u = 0; u < 4; u++)
#pragma unroll
                for (int p = 0; p < 4; p++) acc[g][u][p] = 0.f;

#pragma unroll
        for (int kc = 0; kc < 8; kc++) {
            int kw = kc * 8 + lx;
            unsigned a[4];
            a[0] = hh[GSWZ(row0, kw)];
            a[1] = hh[GSWZ(row0 + 8, kw)];
            a[2] = hh[GSWZ(row0, kw + 4)];
            a[3] = hh[GSWZ(row0 + 8, kw + 4)];
#pragma unroll
            for (int g = 0; g < 3; g++)
#pragma unroll
                for (int u = 0; u < 4; u++) {
                    int n = g * 128 + (jq * 4 + u) * 8 + ly;
                    unsigned b[2];
                    b[0] = Wsh[GSWZ(n, kw)];
                    b[1] = Wsh[GSWZ(n, kw + 4)];
                    mma_f16(acc[g][u], a, b);
                }
        }
        __syncthreads();

        int tok0 = stok[row0];
        int tok1 = stok[row0 + 8];
        const __half* e20 = E2 + (size_t)tok0 * H3;
        const __half* e21 = E2 + (size_t)tok1 * H3;
#pragma unroll
        for (int u = 0; u < 4; u++) {
            int j0 = (jq * 4 + u) * 8 + lx * 2;
            float bir0 = sbih[j0], bhr0 = sbhh[j0];
            float biz0 = sbih[128 + j0], bhz0 = sbhh[128 + j0];
            float bin0 = sbih[256 + j0], bhn0 = sbhh[256 + j0];
            float bir1 = sbih[j0 + 1], bhr1 = sbhh[j0 + 1];
            float biz1 = sbih[128 + j0 + 1], bhz1 = sbhh[128 + j0 + 1];
            float bin1 = sbih[256 + j0 + 1], bhn1 = sbhh[256 + j0 + 1];
            int kw = (jq * 4 + u) * 4 + lx;
#pragma unroll
            for (int rh = 0; rh < 2; rh++) {
                int r = row0 + rh * 8;
                const __half* e2 = rh ? e21 : e20;
                float h2v[2];
#pragma unroll
                for (int i = 0; i < 2; i++) {
                    int p = rh * 2 + i;
                    int j = j0 + i;
                    float gr = __half2float(e2[j]) + (i ? bir1 : bir0) + acc[0][u][p] + (i ? bhr1 : bhr0);
                    float gz = __half2float(e2[128 + j]) + (i ? biz1 : biz0) + acc[1][u][p] + (i ? bhz1 : bhz0);
                    float gn = __half2float(e2[256 + j]) + (i ? bin1 : bin0);
                    float hn = acc[2][u][p] + (i ? bhn1 : bhn0);
                    float rr = 1.f / (1.f + expf(-gr));
                    float zz = 1.f / (1.f + expf(-gz));
                    float nn_ = tanhf(gn + rr * hn);
                    float hp = hreg[u][p];
                    float h2 = (1.f - zz) * nn_ + zz * hp;
                    hreg[u][p] = h2;
                    tacc[u][p] += h2;
                    h2v[i] = h2;
                }
                hh[GSWZ(r, kw)] = pack_h2(h2v[0], h2v[1]);
            }
        }
        __syncthreads();
    }
#pragma unroll
    for (int u = 0; u < 4; u++)
#pragma unroll
        for (int p = 0; p < 4; p++) {
            int r = m0 + row0 + (p >> 1) * 8;
            int j = (jq * 4 + u) * 8 + lx * 2 + (p & 1);
            txt[(size_t)r * 128 + j] = tacc[u][p];
        }
}

// ---------------- generic tf32 GEMM (optional fp16 output) ----------------
template <bool NT, bool OUTH>
__global__ void __launch_bounds__(256) gemm_tf32(
    const float* __restrict__ A, int lda, const float* __restrict__ B, int ldb,
    void* __restrict__ Cv, int ldc, int M, int N, int K) {
    __shared__ float As[64 * 36];
    __shared__ float Bs[5120];
    int tid = threadIdx.x;
    int w = tid >> 5;
    int lane = tid & 31;
    int ly = lane >> 2, lx = lane & 3;
    int bm = blockIdx.x * 64, bn = blockIdx.y * 128;
    float acc[4][2][4];
#pragma unroll
    for (int i = 0; i < 4; i++)
#pragma unroll
        for (int j = 0; j < 2; j++)
#pragma unroll
            for (int q = 0; q < 4; q++) acc[i][j][q] = 0.f;

    for (int kt = 0; kt < K; kt += 32) {
#pragma unroll
        for (int l = 0; l < 2; l++) {
            int li = tid + l * 256;
            int row = li >> 3;
            int kc = (li & 7) * 4;
            float4 v = make_float4(0.f, 0.f, 0.f, 0.f);
            if (bm + row < M) v = *(const float4*)(A + (size_t)(bm + row) * lda + kt + kc);
            float4 t;
            t.x = f2tf(v.x); t.y = f2tf(v.y); t.z = f2tf(v.z); t.w = f2tf(v.w);
            *(float4*)&As[row * 36 + kc] = t;
        }
        if (NT) {
#pragma unroll
            for (int l = 0; l < 4; l++) {
                int li = tid + l * 256;
                int n = li >> 3;
                int kc = (li & 7) * 4;
                float4 v = *(const float4*)(B + (size_t)(bn + n) * ldb + kt + kc);
                float4 t;
                t.x = f2tf(v.x); t.y = f2tf(v.y); t.z = f2tf(v.z); t.w = f2tf(v.w);
                *(float4*)&Bs[n * 40 + kc] = t;
            }
        } else {
#pragma unroll
            for (int l = 0; l < 4; l++) {
                int li = tid + l * 256;
                int k = li >> 5;
                int nc = (li & 31) * 4;
                float4 v = *(const float4*)(B + (size_t)(kt + k) * ldb + bn + nc);
                float4 t;
                t.x = f2tf(v.x); t.y = f2tf(v.y); t.z = f2tf(v.z); t.w = f2tf(v.w);
                *(float4*)&Bs[k * 136 + nc] = t;
            }
        }
        __syncthreads();
#pragma unroll
        for (int kk = 0; kk < 4; kk++) {
            unsigned a[4][4];
#pragma unroll
            for (int mt = 0; mt < 4; mt++) {
                int row = mt * 16 + ly;
                int k = kk * 8 + lx;
                a[mt][0] = __float_as_uint(As[row * 36 + k]);
                a[mt][1] = __float_as_uint(As[(row + 8) * 36 + k]);
                a[mt][2] = __float_as_uint(As[row * 36 + k + 4]);
                a[mt][3] = __float_as_uint(As[(row + 8) * 36 + k + 4]);
            }
            unsigned b[2][2];
#pragma unroll
            for (int nt = 0; nt < 2; nt++) {
                int n = w * 16 + nt * 8 + ly;
                int k = kk * 8 + lx;
                if (NT) {
                    b[nt][0] = __float_as_uint(Bs[n * 40 + k]);
                    b[nt][1] = __float_as_uint(Bs[n * 40 + k + 4]);
                } else {
                    b[nt][0] = __float_as_uint(Bs[k * 136 + n]);
                    b[nt][1] = __float_as_uint(Bs[(k + 4) * 136 + n]);
                }
            }
#pragma unroll
            for (int mt = 0; mt < 4; mt++)
#pragma unroll
                for (int nt = 0; nt < 2; nt++) mma_tf32(acc[mt][nt], a[mt], b[nt]);
        }
        __syncthreads();
    }
#pragma unroll
    for (int mt = 0; mt < 4; mt++)
#pragma unroll
        for (int nt = 0; nt < 2; nt++) {
            int row = bm + mt * 16 + ly;
            int col = bn + w * 16 + nt * 8 + lx * 2;
            if (OUTH) {
                __half* C = (__half*)Cv;
                if (row < M)
                    *(__half2*)(C + (size_t)row * ldc + col) =
                        __floats2half2_rn(acc[mt][nt][0], acc[mt][nt][1]);
                if (row + 8 < M)
                    *(__half2*)(C + (size_t)(row + 8) * ldc + col) =
                        __floats2half2_rn(acc[mt][nt][2], acc[mt][nt][3]);
            } else {
                float* C = (float*)Cv;
                if (row < M) {
                    C[(size_t)row * ldc + col] = acc[mt][nt][0];
                    C[(size_t)row * ldc + col + 1] = acc[mt][nt][1];
                }
                if (row + 8 < M) {
                    C[(size_t)(row + 8) * ldc + col] = acc[mt][nt][2];
                    C[(size_t)(row + 8) * ldc + col + 1] = acc[mt][nt][3];
                }
            }
        }
}

// ---------------- dual-B NN GEMM, fp16 output ----------------
__global__ void __launch_bounds__(256) gemm_tf32_dual(
    const float* __restrict__ A, int lda, const float* __restrict__ B1,
    const float* __restrict__ B2, int ldb, __half* __restrict__ C, int ldc,
    int M, int K) {
    const float* B = blockIdx.y ? B2 : B1;
    int cb = blockIdx.y * 128;
    __shared__ float As[64 * 36];
    __shared__ float Bs[5120];
    int tid = threadIdx.x;
    int w = tid >> 5;
    int lane = tid & 31;
    int ly = lane >> 2, lx = lane & 3;
    int bm = blockIdx.x * 64;
    float acc[4][2][4];
#pragma unroll
    for (int i = 0; i < 4; i++)
#pragma unroll
        for (int j = 0; j < 2; j++)
#pragma unroll
            for (int q = 0; q < 4; q++) acc[i][j][q] = 0.f;

    for (int kt = 0; kt < K; kt += 32) {
#pragma unroll
        for (int l = 0; l < 2; l++) {
            int li = tid + l * 256;
            int row = li >> 3;
            int kc = (li & 7) * 4;
            float4 v = make_float4(0.f, 0.f, 0.f, 0.f);
            if (bm + row < M) v = *(const float4*)(A + (size_t)(bm + row) * lda + kt + kc);
            float4 t;
            t.x = f2tf(v.x); t.y = f2tf(v.y); t.z = f2tf(v.z); t.w = f2tf(v.w);
            *(float4*)&As[row * 36 + kc] = t;
        }
#pragma unroll
        for (int l = 0; l < 4; l++) {
            int li = tid + l * 256;
            int k = li >> 5;
            int nc = (li & 31) * 4;
            float4 v = *(const float4*)(B + (size_t)(kt + k) * ldb + nc);
            float4 t;
            t.x = f2tf(v.x); t.y = f2tf(v.y); t.z = f2tf(v.z); t.w = f2tf(v.w);
            *(float4*)&Bs[k * 136 + nc] = t;
        }
        __syncthreads();
#pragma unroll
        for (int kk = 0; kk < 4; kk++) {
            unsigned a[4][4];
#pragma unroll
            for (int mt = 0; mt < 4; mt++) {
                int row = mt * 16 + ly;
                int k = kk * 8 + lx;
                a[mt][0] = __float_as_uint(As[row * 36 + k]);
                a[mt][1] = __float_as_uint(As[(row + 8) * 36 + k]);
                a[mt][2] = __float_as_uint(As[row * 36 + k + 4]);
                a[mt][3] = __float_as_uint(As[(row + 8) * 36 + k + 4]);
            }
            unsigned b[2][2];
#pragma unroll
            for (int nt = 0; nt < 2; nt++) {
                int n = w * 16 + nt * 8 + ly;
                int k = kk * 8 + lx;
                b[nt][0] = __float_as_uint(Bs[k * 136 + n]);
                b[nt][1] = __float_as_uint(Bs[(k + 4) * 136 + n]);
            }
#pragma unroll
            for (int mt = 0; mt < 4; mt++)
#pragma unroll
                for (int nt = 0; nt < 2; nt++) mma_tf32(acc[mt][nt], a[mt], b[nt]);
        }
        __syncthreads();
    }
#pragma unroll
    for (int mt = 0; mt < 4; mt++)
#pragma unroll
        for (int nt = 0; nt < 2; nt++) {
            int row = bm + mt * 16 + ly;
            int col = cb + w * 16 + nt * 8 + lx * 2;
            if (row < M)
                *(__half2*)(C + (size_t)row * ldc + col) =
                    __floats2half2_rn(acc[mt][nt][0], acc[mt][nt][1]);
            if (row + 8 < M)
                *(__half2*)(C + (size_t)(row + 8) * ldc + col) =
                    __floats2half2_rn(acc[mt][nt][2], acc[mt][nt][3]);
        }
}

// ---------------- fused edge heads (R14 proven: raw order + cp.async W prefetch) ----------------
#define EH_ASW  (64 * 68)
#define EH_WPW  (64 * 136)
#define EH_SMEM ((EH_ASW + 2 * EH_WPW + 1024) * 4)

__global__ void __launch_bounds__(256, 2) k_edge_heads_f16(
    const int* __restrict__ src, const int* __restrict__ dst,
    const __half* __restrict__ pre, const unsigned* __restrict__ w1p,
    const float* __restrict__ bpos, const float* __restrict__ btxt,
    const float* __restrict__ bimg,
    const float* __restrict__ rb1, const float* __restrict__ rw2,
    const float* __restrict__ rb2,
    const float* __restrict__ cb1, const float* __restrict__ cw2,
    const float* __restrict__ cb2,
    float* __restrict__ out) {
    extern __shared__ unsigned shm[];
    unsigned* Asw = shm;
    unsigned* Wrp = Asw + EH_ASW;
    unsigned* Wcp = Wrp + EH_WPW;
    float* red = (float*)(Wcp + EH_WPW);
    __shared__ int ssrc[64];
    __shared__ int sdst[64];
    __shared__ float sbias[384];
    int tid = threadIdx.x;
    int w = tid >> 5;
    int lane = tid & 31;
    int ly = lane >> 2, lx = lane & 3;
    int head = w & 1;
    int q = w >> 1;
    int n0 = q * 32;
    int e0 = blockIdx.x * 64;
    if (tid < 64) { ssrc[tid] = src[e0 + tid]; sdst[tid] = dst[e0 + tid]; }
    for (int i = tid; i < 384; i += 256) {
        int region = i >> 7, j = i & 127;
        const float* bsrc = (region == 0) ? bpos : ((region == 1) ? btxt : bimg);
        sbias[i] = bsrc[j];
    }

    float acc[4][4][4];
#pragma unroll
    for (int i = 0; i < 4; i++)
#pragma unroll
        for (int j = 0; j < 4; j++)
#pragma unroll
            for (int p = 0; p < 4; p++) acc[i][j][p] = 0.f;

    for (int c = 0; c < 3; c++) {
        __syncthreads();
        // prefetch W chunks (both heads) via cp.async; lands during A build
        {
            const unsigned* WgR = w1p + (size_t)c * 8192;
            const unsigned* WgC = w1p + (size_t)(3 + c) * 8192;
#pragma unroll
            for (int l = 0; l < 8; l++) {
                int idx = tid + l * 256;
                int kp = idx >> 5;
                int n4 = (idx & 31) * 4;
                cp_async16(smem_addr(&Wrp[kp * 136 + n4]), WgR + kp * 128 + n4);
                cp_async16(smem_addr(&Wcp[kp * 136 + n4]), WgC + kp * 128 + n4);
            }
        }
        // A tile: 64 edges x 128 feats (chunk c)
#pragma unroll
        for (int l = 0; l < 16; l++) {
            int idx2 = tid + l * 256;
            int m = idx2 >> 6;
            int k2 = (idx2 & 63) * 2;
            int s = ssrc[m], d = sdst[m];
            float2 va = __half22float2(*(const __half2*)(pre + (size_t)s * 768 + c * 256 + k2));
            float2 vb = __half22float2(*(const __half2*)(pre + (size_t)d * 768 + c * 256 + 128 + k2));
            float xx = fmaxf(va.x + vb.x + sbias[c * 128 + k2], 0.f);
            float yy = fmaxf(va.y + vb.y + sbias[c * 128 + k2 + 1], 0.f);
            Asw[m * 68 + (k2 >> 1)] = pack_h2(xx, yy);
        }
        CP_WAIT_ALL();
        __syncthreads();
        const unsigned* Wp = head ? Wcp : Wrp;
#pragma unroll
        for (int kk = 0; kk < 8; kk++) {
            int kp = kk * 8 + lx;
            unsigned b[4][2];
#pragma unroll
            for (int nt = 0; nt < 4; nt++) {
                int n = n0 + nt * 8 + ly;
                b[nt][0] = Wp[kp * 136 + n];
                b[nt][1] = Wp[(kp + 4) * 136 + n];
            }
#pragma unroll
            for (int mt = 0; mt < 4; mt++) {
                int wbase = (mt * 16 + ly) * 68 + kk * 8 + lx;
                unsigned a[4];
                a[0] = Asw[wbase];
                a[1] = Asw[wbase + 8 * 68];
                a[2] = Asw[wbase + 4];
                a[3] = Asw[wbase + 8 * 68 + 4];
#pragma unroll
                for (int nt = 0; nt < 4; nt++) mma_f16(acc[mt][nt], a, b[nt]);
            }
        }
    }

    const float* b1 = head ? cb1 : rb1;
    const float* w2 = head ? cw2 : rw2;
    float p[4][2][2];
#pragma unroll
    for (int mt = 0; mt < 4; mt++)
#pragma unroll
        for (int rr = 0; rr < 2; rr++) { p[mt][rr][0] = 0.f; p[mt][rr][1] = 0.f; }
#pragma unroll
    for (int nt = 0; nt < 4; nt++) {
        int j0 = n0 + nt * 8 + lx * 2;
        float b10 = b1[j0], b11 = b1[j0 + 1];
        float w200 = w2[j0 * 2], w201 = w2[j0 * 2 + 1];
        float w210 = w2[(j0 + 1) * 2], w211 = w2[(j0 + 1) * 2 + 1];
#pragma unroll
        for (int mt = 0; mt < 4; mt++) {
            float h0 = fmaxf(acc[mt][nt][0] + b10, 0.f);
            float h1 = fmaxf(acc[mt][nt][1] + b11, 0.f);
            float h2 = fmaxf(acc[mt][nt][2] + b10, 0.f);
            float h3 = fmaxf(acc[mt][nt][3] + b11, 0.f);
            p[mt][0][0] += h0 * w200 + h1 * w210;
            p[mt][0][1] += h0 * w201 + h1 * w211;
            p[mt][1][0] += h2 * w200 + h3 * w210;
            p[mt][1][1] += h2 * w201 + h3 * w211;
        }
    }
#pragma unroll
    for (int mt = 0; mt < 4; mt++)
#pragma unroll
        for (int rr = 0; rr < 2; rr++)
#pragma unroll
            for (int cl = 0; cl < 2; cl++) {
                float v = p[mt][rr][cl];
                v += __shfl_down_sync(0xffffffffu, v, 2, 4);
                v += __shfl_down_sync(0xffffffffu, v, 1, 4);
                p[mt][rr][cl] = v;
            }
    if (lx == 0) {
#pragma unroll
        for (int mt = 0; mt < 4; mt++)
#pragma unroll
            for (int rr = 0; rr < 2; rr++) {
                int row = mt * 16 + ly + rr * 8;
                red[((head * 4 + q) * 64 + row) * 2 + 0] = p[mt][rr][0];
                red[((head * 4 + q) * 64 + row) * 2 + 1] = p[mt][rr][1];
            }
    }
    __syncthreads();
    if (tid < 128) {
        int m = tid & 63;
        int h = tid >> 6;
        float l0 = 0.f, l1 = 0.f;
#pragma unroll
        for (int qq = 0; qq < 4; qq++) {
            l0 += red[((h * 4 + qq) * 64 + m) * 2 + 0];
            l1 += red[((h * 4 + qq) * 64 + m) * 2 + 1];
        }
        const float* b2 = h ? cb2 : rb2;
        l0 += b2[0];
        l1 += b2[1];
        float mx = fmaxf(l0, l1);
        float lse = mx + logf(expf(l0 - mx) + expf(l1 - mx));
        size_t base = ((size_t)h * Ee + e0 + m) * 2;
        out[base + 0] = l0 - lse;
        out[base + 1] = l1 - lse;
    }
}

// ---------------- launch ----------------
extern "C" void kernel_launch(void* const* d_in, const int* in_sizes, int n_in,
                              void* d_out, int out_size) {
    const float* x     = (const float*)d_in[0];
    const int*   ei    = (const int*)d_in[1];
    const int*   xtext = (const int*)d_in[2];
    const float* img   = (const float*)d_in[3];
    const float* c1w   = (const float*)d_in[4];
    const float* c1b   = (const float*)d_in[5];
    const float* c2w   = (const float*)d_in[6];
    const float* c2b   = (const float*)d_in[7];
    const float* emb   = (const float*)d_in[8];
    const float* wih   = (const float*)d_in[9];
    const float* whh   = (const float*)d_in[10];
    const float* bih   = (const float*)d_in[11];
    const float* bhh   = (const float*)d_in[12];
    const float* lpw   = (const float*)d_in[13];
    const float* lpb   = (const float*)d_in[14];
    const float* ltw   = (const float*)d_in[15];
    const float* ltb   = (const float*)d_in[16];
    const float* liw   = (const float*)d_in[17];
    const float* lib   = (const float*)d_in[18];
    const float* rw1   = (const float*)d_in[19];
    const float* rb1   = (const float*)d_in[20];
    const float* rw2   = (const float*)d_in[21];
    const float* rb2   = (const float*)d_in[22];
    const float* cw1   = (const float*)d_in[23];
    const float* cb1   = (const float*)d_in[24];
    const float* cw2   = (const float*)d_in[25];
    const float* cb2   = (const float*)d_in[26];
    float* out = (float*)d_out;
    const int* srcp = ei;
    const int* dstp = ei + Ee;

    float *p_xw, *p_h1, *p_pos, *p_dinv, *p_txt, *p_nrm;
    __half *p_E2h, *p_preh;
    unsigned* p_w1p;
    int *p_cnt, *p_off, *p_cur, *p_nbr;
    cudaGetSymbolAddress((void**)&p_xw, g_xw);
    cudaGetSymbolAddress((void**)&p_h1, g_h1);
    cudaGetSymbolAddress((void**)&p_pos, g_pos);
    cudaGetSymbolAddress((void**)&p_dinv, g_dinv);
    cudaGetSymbolAddress((void**)&p_cnt, g_cnt);
    cudaGetSymbolAddress((void**)&p_off, g_off);
    cudaGetSymbolAddress((void**)&p_cur, g_cur);
    cudaGetSymbolAddress((void**)&p_nbr, g_nbr);
    cudaGetSymbolAddress((void**)&p_nrm, g_nrm);
    cudaGetSymbolAddress((void**)&p_E2h, g_E2h);
    cudaGetSymbolAddress((void**)&p_txt, g_txt);
    cudaGetSymbolAddress((void**)&p_preh, g_preh);
    cudaGetSymbolAddress((void**)&p_w1p, g_w1p);

    static cudaStream_t sB = 0, sC = 0;
    static cudaEvent_t ev0 = 0, evB = 0, evC = 0, evX = 0;
    if (!sB) {
        cudaStreamCreateWithFlags(&sB, cudaStreamNonBlocking);
        cudaStreamCreateWithFlags(&sC, cudaStreamNonBlocking);
        cudaEventCreateWithFlags(&ev0, cudaEventDisableTiming);
        cudaEventCreateWithFlags(&evB, cudaEventDisableTiming);
        cudaEventCreateWithFlags(&evC, cudaEventDisableTiming);
        cudaEventCreateWithFlags(&evX, cudaEventDisableTiming);
        cudaFuncSetAttribute(k_gru_fused, cudaFuncAttributeMaxDynamicSharedMemorySize, GRU_SMEM);
        cudaFuncSetAttribute(k_edge_heads_f16, cudaFuncAttributeMaxDynamicSharedMemorySize, EH_SMEM);
    }

    // fork
    cudaEventRecord(ev0, 0);
    cudaStreamWaitEvent(sB, ev0, 0);
    cudaStreamWaitEvent(sC, ev0, 0);

    // ---- stream B: text chain ----
    {
        dim3 g((Vv + 63) / 64, H3 / 128);
        gemm_tf32<true, true><<<g, 256, 0, sB>>>(emb, Tt, wih, Tt, p_E2h, H3, Vv, H3, Tt);
        k_gru_fused<<<Nn / 32, 256, GRU_SMEM, sB>>>(xtext, p_E2h, whh, bih, bhh, p_txt);
        dim3 gd((Nn + 63) / 64, 2);
        gemm_tf32_dual<<<gd, 256, 0, sB>>>(p_txt, 128, ltw, ltw + 128 * 128, 128,
                                           p_preh + 256, 768, Nn, 128);
        cudaEventRecord(evB, sB);
    }

    // ---- stream C: xw1, W1 pack, img pre pair ----
    {
        k_xw1<<<Nn, 128, 0, sC>>>(x, c1w, p_xw);
        cudaEventRecord(evX, sC);
        k_packw<<<(2 * 3 * 64 * 128 + 255) / 256, 256, 0, sC>>>(rw1, cw1, p_w1p);
        dim3 gd((Nn + 63) / 64, 2);
        gemm_tf32_dual<<<gd, 256, 0, sC>>>(img, 256, liw, liw + 256 * 128, 128,
                                           p_preh + 512, 768, Nn, 256);
        cudaEventRecord(evC, sC);
    }

    // ---- default stream: CSR build || xw1, GCN gathers, pos pre pair ----
    cudaMemsetAsync(p_cnt, 0, Nn * sizeof(int));
    cudaMemsetAsync(p_cur, 0, Nn * sizeof(int));
    k_hist<<<(Ee + 255) / 256, 256>>>(dstp, p_cnt);
    k_scan<<<1, 1024>>>(p_cnt, p_off, p_dinv);
    k_fill<<<(Ee + 255) / 256, 256>>>(srcp, dstp, p_dinv, p_off, p_cur, p_nbr, p_nrm);

    cudaStreamWaitEvent(0, evX, 0);
    k_gather<<<Nn / 8, 256>>>(p_xw, p_nbr, p_nrm, p_off, p_dinv, c1b, p_h1);

    {
        dim3 g((Nn + 63) / 64, 1);
        gemm_tf32<false, false><<<g, 256>>>(p_h1, 128, c2w, 128, p_xw, 128, Nn, 128, 128);
    }
    k_gather<<<Nn / 8, 256>>>(p_xw, p_nbr, p_nrm, p_off, p_dinv, c2b, p_pos);

    {
        dim3 gd((Nn + 63) / 64, 2);
        gemm_tf32_dual<<<gd, 256>>>(p_pos, 128, lpw, lpw + 128 * 128, 128,
                                    p_preh + 0, 768, Nn, 128);
    }

    // join
    cudaStreamWaitEvent(0, evB, 0);
    cudaStreamWaitEvent(0, evC, 0);

    // fused edge heads
    k_edge_heads_f16<<<Ee / 64, 256, EH_SMEM>>>(srcp, dstp, p_preh, p_w1p,
                                                lpb, ltb, lib,
                                                rb1, rw2, rb2, cb1, cw2, cb2, out);
    (void)in_sizes; (void)n_in; (void)out_size;
}

// round 17
// speedup vs baseline: 1.0433x; 1.0085x over previous
#include <cuda_runtime.h>
#include <cuda_fp16.h>
#include <math.h>

#define Nn 20000
#define Ee 320000
#define Ll 16
#define Tt 64
#define Hh 128
#define Vv 32000
#define H3 384
#define NH (Nn*Hh)

// ---------------- scratch ----------------
__device__ __half g_xwh[NH];
__device__ float g_h1[NH];
__device__ float g_pos[NH];
__device__ float g_dinv[Nn];
__device__ int   g_cnt[Nn];
__device__ int   g_off[Nn + 1];
__device__ int   g_cur[Nn];
__device__ int   g_nbr[Ee];
__device__ float g_nrm[Ee];
__device__ __half g_E2h[Vv*H3];
__device__ float g_txt[NH];
__device__ __half g_preh[Nn*768];
__device__ unsigned g_w1p[2 * 3 * 64 * 128];

// ---------------- helpers ----------------
__device__ __forceinline__ float f2tf(float x) {
    unsigned u;
    asm("cvt.rna.tf32.f32 %0, %1;" : "=r"(u) : "f"(x));
    return __uint_as_float(u);
}
__device__ __forceinline__ unsigned pack_h2(float lo, float hi) {
    unsigned u;
    asm("cvt.rn.f16x2.f32 %0, %1, %2;" : "=r"(u) : "f"(hi), "f"(lo));
    return u;
}
__device__ __forceinline__ unsigned smem_addr(const void* p) {
    unsigned a;
    asm("{ .reg .u64 t; cvta.to.shared.u64 t, %1; cvt.u32.u64 %0, t; }" : "=r"(a) : "l"(p));
    return a;
}
__device__ __forceinline__ void cp_async16(unsigned saddr, const void* g) {
    asm volatile("cp.async.cg.shared.global [%0], [%1], 16;" :: "r"(saddr), "l"(g) : "memory");
}
#define CP_WAIT_ALL() asm volatile("cp.async.wait_all;" ::: "memory")

__device__ __forceinline__ void mma_tf32(float* d, const unsigned* a, const unsigned* b) {
    asm volatile(
        "mma.sync.aligned.m16n8k8.row.col.f32.tf32.tf32.f32 "
        "{%0,%1,%2,%3},{%4,%5,%6,%7},{%8,%9},{%0,%1,%2,%3};"
        : "+f"(d[0]), "+f"(d[1]), "+f"(d[2]), "+f"(d[3])
        : "r"(a[0]), "r"(a[1]), "r"(a[2]), "r"(a[3]), "r"(b[0]), "r"(b[1]));
}

__device__ __forceinline__ void mma_f16(float* d, const unsigned* a, const unsigned* b) {
    asm volatile(
        "mma.sync.aligned.m16n8k16.row.col.f32.f16.f16.f32 "
        "{%0,%1,%2,%3},{%4,%5,%6,%7},{%8,%9},{%0,%1,%2,%3};"
        : "+f"(d[0]), "+f"(d[1]), "+f"(d[2]), "+f"(d[3])
        : "r"(a[0]), "r"(a[1]), "r"(a[2]), "r"(a[3]), "r"(b[0]), "r"(b[1]));
}

// ---------------- CSR build ----------------
__global__ void k_hist(const int* __restrict__ dst, int* __restrict__ cnt) {
    int e = blockIdx.x * blockDim.x + threadIdx.x;
    if (e < Ee) atomicAdd(&cnt[dst[e]], 1);
}

__global__ void __launch_bounds__(1024) k_scan(const int* __restrict__ cnt,
                                               int* __restrict__ off,
                                               float* __restrict__ dinv) {
    __shared__ int part[1024];
    int t = threadIdx.x;
    int base = t * 20;
    int loc[20];
    int s = 0;
#pragma unroll
    for (int i = 0; i < 20; i++) {
        int idx = base + i;
        int v = (idx < Nn) ? cnt[idx] : 0;
        loc[i] = s;
        s += v;
        if (idx < Nn) dinv[idx] = rsqrtf((float)v + 1.0f);
    }
    part[t] = s;
    __syncthreads();
    for (int d = 1; d < 1024; d <<= 1) {
        int o = (t >= d) ? part[t - d] : 0;
        __syncthreads();
        part[t] += o;
        __syncthreads();
    }
    int pre = part[t] - s;
#pragma unroll
    for (int i = 0; i < 20; i++) {
        int idx = base + i;
        if (idx < Nn) off[idx] = pre + loc[i];
    }
    if (t == 1023) off[Nn] = Ee;
}

__global__ void k_fill(const int* __restrict__ src, const int* __restrict__ dst,
                       const float* __restrict__ dinv, const int* __restrict__ off,
                       int* __restrict__ cur, int* __restrict__ nbr,
                       float* __restrict__ nrm) {
    int e = blockIdx.x * blockDim.x + threadIdx.x;
    if (e >= Ee) return;
    int s = src[e], d = dst[e];
    int p = atomicAdd(&cur[d], 1);
    int idx = off[d] + p;
    nbr[idx] = s;
    nrm[idx] = dinv[s] * dinv[d];
}

// gather: 8 nodes/block, 32 threads/node, fp16 rows (uint2 = 4 halves), unroll x2
__global__ void __launch_bounds__(256) k_gather(
    const __half* __restrict__ xw, const int* __restrict__ nbr,
    const float* __restrict__ nrm, const int* __restrict__ off,
    const float* __restrict__ dinv, const float* __restrict__ b,
    float* __restrict__ out) {
    int n = blockIdx.x * 8 + (threadIdx.x >> 5);
    int j = threadIdx.x & 31;            // 4-half column group
    const uint2* xw2 = (const uint2*)xw; // row stride 32 uint2
    int beg = off[n], end = off[n + 1];
    float4 acc = make_float4(0.f, 0.f, 0.f, 0.f);
    int i = beg;
    for (; i + 2 <= end; i += 2) {
        int s0 = nbr[i], s1 = nbr[i + 1];
        float w0 = nrm[i], w1 = nrm[i + 1];
        uint2 u0 = xw2[(size_t)s0 * 32 + j];
        uint2 u1 = xw2[(size_t)s1 * 32 + j];
        float2 a0 = __half22float2(*(__half2*)&u0.x);
        float2 a1 = __half22float2(*(__half2*)&u0.y);
        float2 b0 = __half22float2(*(__half2*)&u1.x);
        float2 b1 = __half22float2(*(__half2*)&u1.y);
        acc.x += a0.x * w0 + b0.x * w1;
        acc.y += a0.y * w0 + b0.y * w1;
        acc.z += a1.x * w0 + b1.x * w1;
        acc.w += a1.y * w0 + b1.y * w1;
    }
    if (i < end) {
        int s0 = nbr[i];
        float w0 = nrm[i];
        uint2 u0 = xw2[(size_t)s0 * 32 + j];
        float2 a0 = __half22float2(*(__half2*)&u0.x);
        float2 a1 = __half22float2(*(__half2*)&u0.y);
        acc.x += a0.x * w0;
        acc.y += a0.y * w0;
        acc.z += a1.x * w0;
        acc.w += a1.y * w0;
    }
    float di = dinv[n];
    float sc = di * di;
    uint2 us = xw2[(size_t)n * 32 + j];
    float2 s0f = __half22float2(*(__half2*)&us.x);
    float2 s1f = __half22float2(*(__half2*)&us.y);
    float4 bb = *(const float4*)(b + j * 4);
    float4 o;
    o.x = fmaxf(acc.x + s0f.x * sc + bb.x, 0.f);
    o.y = fmaxf(acc.y + s0f.y * sc + bb.y, 0.f);
    o.z = fmaxf(acc.z + s1f.x * sc + bb.z, 0.f);
    o.w = fmaxf(acc.w + s1f.y * sc + bb.w, 0.f);
    ((float4*)out)[(size_t)n * 32 + j] = o;
}

__global__ void k_xw1(const float* __restrict__ x, const float* __restrict__ w,
                      __half* __restrict__ out) {
    int n = blockIdx.x;
    int h = threadIdx.x;
    __shared__ float xs[8];
    if (threadIdx.x < 8) xs[threadIdx.x] = x[n * 8 + threadIdx.x];
    __syncthreads();
    float s = 0.f;
#pragma unroll
    for (int f = 0; f < 8; f++) s += xs[f] * w[f * 128 + h];
    out[n * 128 + h] = __float2half(s);
}

__global__ void k_packw(const float* __restrict__ rw1, const float* __restrict__ cw1,
                        unsigned* __restrict__ w1p) {
    int i = blockIdx.x * 256 + threadIdx.x;
    if (i >= 2 * 3 * 64 * 128) return;
    int head = i / 24576;
    int r = i % 24576;
    int c = r / 8192;
    int kp = (r >> 7) & 63;
    int n = r & 127;
    const float* W = head ? cw1 : rw1;
    int k = c * 128 + 2 * kp;
    w1p[i] = pack_h2(W[(size_t)k * 128 + n], W[(size_t)(k + 1) * 128 + n]);
}

// ---------------- fused 16-step GRU (proven) ----------------
#define GRU_SMEM ((384 * 64 + 32 * 64) * 4)
#define GSWZ(r, kw) ((r) * 64 + ((kw) ^ (((r) & 7) << 2)))

__global__ void __launch_bounds__(256, 2) k_gru_fused(
    const int* __restrict__ xtext, const __half* __restrict__ E2,
    const float* __restrict__ whh, const float* __restrict__ bih,
    const float* __restrict__ bhh, float* __restrict__ txt) {
    extern __shared__ unsigned gsm[];
    unsigned* Wsh = gsm;
    unsigned* hh = Wsh + 384 * 64;
    __shared__ int stok[32];
    __shared__ float sbih[384], sbhh[384];
    int tid = threadIdx.x;
    int w = tid >> 5, lane = tid & 31;
    int ly = lane >> 2, lx = lane & 3;
    int mt = w >> 2;
    int jq = w & 3;
    int m0 = blockIdx.x * 32;

    for (int i = tid; i < 384 * 32; i += 256) {
        int n = i >> 5;
        int kc4 = (i & 31) * 4;
        float4 v = *(const float4*)(whh + (size_t)n * 128 + kc4);
        int kw = kc4 >> 1;
        Wsh[GSWZ(n, kw)] = pack_h2(v.x, v.y);
        Wsh[GSWZ(n, kw + 1)] = pack_h2(v.z, v.w);
    }
    for (int i = tid; i < 32 * 64; i += 256) hh[i] = 0u;
    for (int i = tid; i < 384; i += 256) { sbih[i] = bih[i]; sbhh[i] = bhh[i]; }

    float tacc[4][4];
    float hreg[4][4];
#pragma unroll
    for (int u = 0; u < 4; u++)
#pragma unroll
        for (int p = 0; p < 4; p++) { tacc[u][p] = 0.f; hreg[u][p] = 0.f; }

    int row0 = mt * 16 + ly;
    __syncthreads();

    for (int step = 0; step < Ll; step++) {
        if (tid < 32) stok[tid] = xtext[(m0 + tid) * Ll + step];
        float acc[3][4][4];
#pragma unroll
        for (int g = 0; g < 3; g++)
#pragma unroll
            for (int u = 0; u < 4; u++)
#pragma unroll
                for (int p = 0; p < 4; p++) acc[g][u][p] = 0.f;

#pragma unroll
        for (int kc = 0; kc < 8; kc++) {
            int kw = kc * 8 + lx;
            unsigned a[4];
            a[0] = hh[GSWZ(row0, kw)];
            a[1] = hh[GSWZ(row0 + 8, kw)];
            a[2] = hh[GSWZ(row0, kw + 4)];
            a[3] = hh[GSWZ(row0 + 8, kw + 4)];
#pragma unroll
            for (int g = 0; g < 3; g++)
#pragma unroll
                for (int u = 0; u < 4; u++) {
                    int n = g * 128 + (jq * 4 + u) * 8 + ly;
                    unsigned b[2];
                    b[0] = Wsh[GSWZ(n, kw)];
                    b[1] = Wsh[GSWZ(n, kw + 4)];
                    mma_f16(acc[g][u], a, b);
                }
        }
        __syncthreads();

        int tok0 = stok[row0];
        int tok1 = stok[row0 + 8];
        const __half* e20 = E2 + (size_t)tok0 * H3;
        const __half* e21 = E2 + (size_t)tok1 * H3;
#pragma unroll
        for (int u = 0; u < 4; u++) {
            int j0 = (jq * 4 + u) * 8 + lx * 2;
            float bir0 = sbih[j0], bhr0 = sbhh[j0];
            float biz0 = sbih[128 + j0], bhz0 = sbhh[128 + j0];
            float bin0 = sbih[256 + j0], bhn0 = sbhh[256 + j0];
            float bir1 = sbih[j0 + 1], bhr1 = sbhh[j0 + 1];
            float biz1 = sbih[128 + j0 + 1], bhz1 = sbhh[128 + j0 + 1];
            float bin1 = sbih[256 + j0 + 1], bhn1 = sbhh[256 + j0 + 1];
            int kw = (jq * 4 + u) * 4 + lx;
#pragma unroll
            for (int rh = 0; rh < 2; rh++) {
                int r = row0 + rh * 8;
                const __half* e2 = rh ? e21 : e20;
                float h2v[2];
#pragma unroll
                for (int i = 0; i < 2; i++) {
                    int p = rh * 2 + i;
                    int j = j0 + i;
                    float gr = __half2float(e2[j]) + (i ? bir1 : bir0) + acc[0][u][p] + (i ? bhr1 : bhr0);
                    float gz = __half2float(e2[128 + j]) + (i ? biz1 : biz0) + acc[1][u][p] + (i ? bhz1 : bhz0);
                    float gn = __half2float(e2[256 + j]) + (i ? bin1 : bin0);
                    float hn = acc[2][u][p] + (i ? bhn1 : bhn0);
                    float rr = 1.f / (1.f + expf(-gr));
                    float zz = 1.f / (1.f + expf(-gz));
                    float nn_ = tanhf(gn + rr * hn);
                    float hp = hreg[u][p];
                    float h2 = (1.f - zz) * nn_ + zz * hp;
                    hreg[u][p] = h2;
                    tacc[u][p] += h2;
                    h2v[i] = h2;
                }
                hh[GSWZ(r, kw)] = pack_h2(h2v[0], h2v[1]);
            }
        }
        __syncthreads();
    }
#pragma unroll
    for (int u = 0; u < 4; u++)
#pragma unroll
        for (int p = 0; p < 4; p++) {
            int r = m0 + row0 + (p >> 1) * 8;
            int j = (jq * 4 + u) * 8 + lx * 2 + (p & 1);
            txt[(size_t)r * 128 + j] = tacc[u][p];
        }
}

// ---------------- generic tf32 GEMM (optional fp16 output) ----------------
template <bool NT, bool OUTH>
__global__ void __launch_bounds__(256) gemm_tf32(
    const float* __restrict__ A, int lda, const float* __restrict__ B, int ldb,
    void* __restrict__ Cv, int ldc, int M, int N, int K) {
    __shared__ float As[64 * 36];
    __shared__ float Bs[5120];
    int tid = threadIdx.x;
    int w = tid >> 5;
    int lane = tid & 31;
    int ly = lane >> 2, lx = lane & 3;
    int bm = blockIdx.x * 64, bn = blockIdx.y * 128;
    float acc[4][2][4];
#pragma unroll
    for (int i = 0; i < 4; i++)
#pragma unroll
        for (int j = 0; j < 2; j++)
#pragma unroll
            for (int q = 0; q < 4; q++) acc[i][j][q] = 0.f;

    for (int kt = 0; kt < K; kt += 32) {
#pragma unroll
        for (int l = 0; l < 2; l++) {
            int li = tid + l * 256;
            int row = li >> 3;
            int kc = (li & 7) * 4;
            float4 v = make_float4(0.f, 0.f, 0.f, 0.f);
            if (bm + row < M) v = *(const float4*)(A + (size_t)(bm + row) * lda + kt + kc);
            float4 t;
            t.x = f2tf(v.x); t.y = f2tf(v.y); t.z = f2tf(v.z); t.w = f2tf(v.w);
            *(float4*)&As[row * 36 + kc] = t;
        }
        if (NT) {
#pragma unroll
            for (int l = 0; l < 4; l++) {
                int li = tid + l * 256;
                int n = li >> 3;
                int kc = (li & 7) * 4;
                float4 v = *(const float4*)(B + (size_t)(bn + n) * ldb + kt + kc);
                float4 t;
                t.x = f2tf(v.x); t.y = f2tf(v.y); t.z = f2tf(v.z); t.w = f2tf(v.w);
                *(float4*)&Bs[n * 40 + kc] = t;
            }
        } else {
#pragma unroll
            for (int l = 0; l < 4; l++) {
                int li = tid + l * 256;
                int k = li >> 5;
                int nc = (li & 31) * 4;
                float4 v = *(const float4*)(B + (size_t)(kt + k) * ldb + bn + nc);
                float4 t;
                t.x = f2tf(v.x); t.y = f2tf(v.y); t.z = f2tf(v.z); t.w = f2tf(v.w);
                *(float4*)&Bs[k * 136 + nc] = t;
            }
        }
        __syncthreads();
#pragma unroll
        for (int kk = 0; kk < 4; kk++) {
            unsigned a[4][4];
#pragma unroll
            for (int mt = 0; mt < 4; mt++) {
                int row = mt * 16 + ly;
                int k = kk * 8 + lx;
                a[mt][0] = __float_as_uint(As[row * 36 + k]);
                a[mt][1] = __float_as_uint(As[(row + 8) * 36 + k]);
                a[mt][2] = __float_as_uint(As[row * 36 + k + 4]);
                a[mt][3] = __float_as_uint(As[(row + 8) * 36 + k + 4]);
            }
            unsigned b[2][2];
#pragma unroll
            for (int nt = 0; nt < 2; nt++) {
                int n = w * 16 + nt * 8 + ly;
                int k = kk * 8 + lx;
                if (NT) {
                    b[nt][0] = __float_as_uint(Bs[n * 40 + k]);
                    b[nt][1] = __float_as_uint(Bs[n * 40 + k + 4]);
                } else {
                    b[nt][0] = __float_as_uint(Bs[k * 136 + n]);
                    b[nt][1] = __float_as_uint(Bs[(k + 4) * 136 + n]);
                }
            }
#pragma unroll
            for (int mt = 0; mt < 4; mt++)
#pragma unroll
                for (int nt = 0; nt < 2; nt++) mma_tf32(acc[mt][nt], a[mt], b[nt]);
        }
        __syncthreads();
    }
#pragma unroll
    for (int mt = 0; mt < 4; mt++)
#pragma unroll
        for (int nt = 0; nt < 2; nt++) {
            int row = bm + mt * 16 + ly;
            int col = bn + w * 16 + nt * 8 + lx * 2;
            if (OUTH) {
                __half* C = (__half*)Cv;
                if (row < M)
                    *(__half2*)(C + (size_t)row * ldc + col) =
                        __floats2half2_rn(acc[mt][nt][0], acc[mt][nt][1]);
                if (row + 8 < M)
                    *(__half2*)(C + (size_t)(row + 8) * ldc + col) =
                        __floats2half2_rn(acc[mt][nt][2], acc[mt][nt][3]);
            } else {
                float* C = (float*)Cv;
                if (row < M) {
                    C[(size_t)row * ldc + col] = acc[mt][nt][0];
                    C[(size_t)row * ldc + col + 1] = acc[mt][nt][1];
                }
                if (row + 8 < M) {
                    C[(size_t)(row + 8) * ldc + col] = acc[mt][nt][2];
                    C[(size_t)(row + 8) * ldc + col + 1] = acc[mt][nt][3];
                }
            }
        }
}

// ---------------- dual-B NN GEMM, fp16 output ----------------
__global__ void __launch_bounds__(256) gemm_tf32_dual(
    const float* __restrict__ A, int lda, const float* __restrict__ B1,
    const float* __restrict__ B2, int ldb, __half* __restrict__ C, int ldc,
    int M, int K) {
    const float* B = blockIdx.y ? B2 : B1;
    int cb = blockIdx.y * 128;
    __shared__ float As[64 * 36];
    __shared__ float Bs[5120];
    int tid = threadIdx.x;
    int w = tid >> 5;
    int lane = tid & 31;
    int ly = lane >> 2, lx = lane & 3;
    int bm = blockIdx.x * 64;
    float acc[4][2][4];
#pragma unroll
    for (int i = 0; i < 4; i++)
#pragma unroll
        for (int j = 0; j < 2; j++)
#pragma unroll
            for (int q = 0; q < 4; q++) acc[i][j][q] = 0.f;

    for (int kt = 0; kt < K; kt += 32) {
#pragma unroll
        for (int l = 0; l < 2; l++) {
            int li = tid + l * 256;
            int row = li >> 3;
            int kc = (li & 7) * 4;
            float4 v = make_float4(0.f, 0.f, 0.f, 0.f);
            if (bm + row < M) v = *(const float4*)(A + (size_t)(bm + row) * lda + kt + kc);
            float4 t;
            t.x = f2tf(v.x); t.y = f2tf(v.y); t.z = f2tf(v.z); t.w = f2tf(v.w);
            *(float4*)&As[row * 36 + kc] = t;
        }
#pragma unroll
        for (int l = 0; l < 4; l++) {
            int li = tid + l * 256;
            int k = li >> 5;
            int nc = (li & 31) * 4;
            float4 v = *(const float4*)(B + (size_t)(kt + k) * ldb + nc);
            float4 t;
            t.x = f2tf(v.x); t.y = f2tf(v.y); t.z = f2tf(v.z); t.w = f2tf(v.w);
            *(float4*)&Bs[k * 136 + nc] = t;
        }
        __syncthreads();
#pragma unroll
        for (int kk = 0; kk < 4; kk++) {
            unsigned a[4][4];
#pragma unroll
            for (int mt = 0; mt < 4; mt++) {
                int row = mt * 16 + ly;
                int k = kk * 8 + lx;
                a[mt][0] = __float_as_uint(As[row * 36 + k]);
                a[mt][1] = __float_as_uint(As[(row + 8) * 36 + k]);
                a[mt][2] = __float_as_uint(As[row * 36 + k + 4]);
                a[mt][3] = __float_as_uint(As[(row + 8) * 36 + k + 4]);
            }
            unsigned b[2][2];
#pragma unroll
            for (int nt = 0; nt < 2; nt++) {
                int n = w * 16 + nt * 8 + ly;
                int k = kk * 8 + lx;
                b[nt][0] = __float_as_uint(Bs[k * 136 + n]);
                b[nt][1] = __float_as_uint(Bs[(k + 4) * 136 + n]);
            }
#pragma unroll
            for (int mt = 0; mt < 4; mt++)
#pragma unroll
                for (int nt = 0; nt < 2; nt++) mma_tf32(acc[mt][nt], a[mt], b[nt]);
        }
        __syncthreads();
    }
#pragma unroll
    for (int mt = 0; mt < 4; mt++)
#pragma unroll
        for (int nt = 0; nt < 2; nt++) {
            int row = bm + mt * 16 + ly;
            int col = cb + w * 16 + nt * 8 + lx * 2;
            if (row < M)
                *(__half2*)(C + (size_t)row * ldc + col) =
                    __floats2half2_rn(acc[mt][nt][0], acc[mt][nt][1]);
            if (row + 8 < M)
                *(__half2*)(C + (size_t)(row + 8) * ldc + col) =
                    __floats2half2_rn(acc[mt][nt][2], acc[mt][nt][3]);
        }
}

// ---------------- fused edge heads (proven) ----------------
#define EH_ASW  (64 * 68)
#define EH_WPW  (64 * 136)
#define EH_SMEM ((EH_ASW + 2 * EH_WPW + 1024) * 4)

__global__ void __launch_bounds__(256, 2) k_edge_heads_f16(
    const int* __restrict__ src, const int* __restrict__ dst,
    const __half* __restrict__ pre, const unsigned* __restrict__ w1p,
    const float* __restrict__ bpos, const float* __restrict__ btxt,
    const float* __restrict__ bimg,
    const float* __restrict__ rb1, const float* __restrict__ rw2,
    const float* __restrict__ rb2,
    const float* __restrict__ cb1, const float* __restrict__ cw2,
    const float* __restrict__ cb2,
    float* __restrict__ out) {
    extern __shared__ unsigned shm[];
    unsigned* Asw = shm;
    unsigned* Wrp = Asw + EH_ASW;
    unsigned* Wcp = Wrp + EH_WPW;
    float* red = (float*)(Wcp + EH_WPW);
    __shared__ int ssrc[64];
    __shared__ int sdst[64];
    __shared__ float sbias[384];
    int tid = threadIdx.x;
    int w = tid >> 5;
    int lane = tid & 31;
    int ly = lane >> 2, lx = lane & 3;
    int head = w & 1;
    int q = w >> 1;
    int n0 = q * 32;
    int e0 = blockIdx.x * 64;
    if (tid < 64) { ssrc[tid] = src[e0 + tid]; sdst[tid] = dst[e0 + tid]; }
    for (int i = tid; i < 384; i += 256) {
        int region = i >> 7, j = i & 127;
        const float* bsrc = (region == 0) ? bpos : ((region == 1) ? btxt : bimg);
        sbias[i] = bsrc[j];
    }

    float acc[4][4][4];
#pragma unroll
    for (int i = 0; i < 4; i++)
#pragma unroll
        for (int j = 0; j < 4; j++)
#pragma unroll
            for (int p = 0; p < 4; p++) acc[i][j][p] = 0.f;

    for (int c = 0; c < 3; c++) {
        __syncthreads();
        {
            const unsigned* WgR = w1p + (size_t)c * 8192;
            const unsigned* WgC = w1p + (size_t)(3 + c) * 8192;
#pragma unroll
            for (int l = 0; l < 8; l++) {
                int idx = tid + l * 256;
                int kp = idx >> 5;
                int n4 = (idx & 31) * 4;
                cp_async16(smem_addr(&Wrp[kp * 136 + n4]), WgR + kp * 128 + n4);
                cp_async16(smem_addr(&Wcp[kp * 136 + n4]), WgC + kp * 128 + n4);
            }
        }
#pragma unroll
        for (int l = 0; l < 16; l++) {
            int idx2 = tid + l * 256;
            int m = idx2 >> 6;
            int k2 = (idx2 & 63) * 2;
            int s = ssrc[m], d = sdst[m];
            float2 va = __half22float2(*(const __half2*)(pre + (size_t)s * 768 + c * 256 + k2));
            float2 vb = __half22float2(*(const __half2*)(pre + (size_t)d * 768 + c * 256 + 128 + k2));
            float xx = fmaxf(va.x + vb.x + sbias[c * 128 + k2], 0.f);
            float yy = fmaxf(va.y + vb.y + sbias[c * 128 + k2 + 1], 0.f);
            Asw[m * 68 + (k2 >> 1)] = pack_h2(xx, yy);
        }
        CP_WAIT_ALL();
        __syncthreads();
        const unsigned* Wp = head ? Wcp : Wrp;
#pragma unroll
        for (int kk = 0; kk < 8; kk++) {
            int kp = kk * 8 + lx;
            unsigned b[4][2];
#pragma unroll
            for (int nt = 0; nt < 4; nt++) {
                int n = n0 + nt * 8 + ly;
                b[nt][0] = Wp[kp * 136 + n];
                b[nt][1] = Wp[(kp + 4) * 136 + n];
            }
#pragma unroll
            for (int mt = 0; mt < 4; mt++) {
                int wbase = (mt * 16 + ly) * 68 + kk * 8 + lx;
                unsigned a[4];
                a[0] = Asw[wbase];
                a[1] = Asw[wbase + 8 * 68];
                a[2] = Asw[wbase + 4];
                a[3] = Asw[wbase + 8 * 68 + 4];
#pragma unroll
                for (int nt = 0; nt < 4; nt++) mma_f16(acc[mt][nt], a, b[nt]);
            }
        }
    }

    const float* b1 = head ? cb1 : rb1;
    const float* w2 = head ? cw2 : rw2;
    float p[4][2][2];
#pragma unroll
    for (int mt = 0; mt < 4; mt++)
#pragma unroll
        for (int rr = 0; rr < 2; rr++) { p[mt][rr][0] = 0.f; p[mt][rr][1] = 0.f; }
#pragma unroll
    for (int nt = 0; nt < 4; nt++) {
        int j0 = n0 + nt * 8 + lx * 2;
        float b10 = b1[j0], b11 = b1[j0 + 1];
        float w200 = w2[j0 * 2], w201 = w2[j0 * 2 + 1];
        float w210 = w2[(j0 + 1) * 2], w211 = w2[(j0 + 1) * 2 + 1];
#pragma unroll
        for (int mt = 0; mt < 4; mt++) {
            float h0 = fmaxf(acc[mt][nt][0] + b10, 0.f);
            float h1 = fmaxf(acc[mt][nt][1] + b11, 0.f);
            float h2 = fmaxf(acc[mt][nt][2] + b10, 0.f);
            float h3 = fmaxf(acc[mt][nt][3] + b11, 0.f);
            p[mt][0][0] += h0 * w200 + h1 * w210;
            p[mt][0][1] += h0 * w201 + h1 * w211;
            p[mt][1][0] += h2 * w200 + h3 * w210;
            p[mt][1][1] += h2 * w201 + h3 * w211;
        }
    }
#pragma unroll
    for (int mt = 0; mt < 4; mt++)
#pragma unroll
        for (int rr = 0; rr < 2; rr++)
#pragma unroll
            for (int cl = 0; cl < 2; cl++) {
                float v = p[mt][rr][cl];
                v += __shfl_down_sync(0xffffffffu, v, 2, 4);
                v += __shfl_down_sync(0xffffffffu, v, 1, 4);
                p[mt][rr][cl] = v;
            }
    if (lx == 0) {
#pragma unroll
        for (int mt = 0; mt < 4; mt++)
#pragma unroll
            for (int rr = 0; rr < 2; rr++) {
                int row = mt * 16 + ly + rr * 8;
                red[((head * 4 + q) * 64 + row) * 2 + 0] = p[mt][rr][0];
                red[((head * 4 + q) * 64 + row) * 2 + 1] = p[mt][rr][1];
            }
    }
    __syncthreads();
    if (tid < 128) {
        int m = tid & 63;
        int h = tid >> 6;
        float l0 = 0.f, l1 = 0.f;
#pragma unroll
        for (int qq = 0; qq < 4; qq++) {
            l0 += red[((h * 4 + qq) * 64 + m) * 2 + 0];
            l1 += red[((h * 4 + qq) * 64 + m) * 2 + 1];
        }
        const float* b2 = h ? cb2 : rb2;
        l0 += b2[0];
        l1 += b2[1];
        float mx = fmaxf(l0, l1);
        float lse = mx + logf(expf(l0 - mx) + expf(l1 - mx));
        size_t base = ((size_t)h * Ee + e0 + m) * 2;
        out[base + 0] = l0 - lse;
        out[base + 1] = l1 - lse;
    }
}

// ---------------- launch ----------------
extern "C" void kernel_launch(void* const* d_in, const int* in_sizes, int n_in,
                              void* d_out, int out_size) {
    const float* x     = (const float*)d_in[0];
    const int*   ei    = (const int*)d_in[1];
    const int*   xtext = (const int*)d_in[2];
    const float* img   = (const float*)d_in[3];
    const float* c1w   = (const float*)d_in[4];
    const float* c1b   = (const float*)d_in[5];
    const float* c2w   = (const float*)d_in[6];
    const float* c2b   = (const float*)d_in[7];
    const float* emb   = (const float*)d_in[8];
    const float* wih   = (const float*)d_in[9];
    const float* whh   = (const float*)d_in[10];
    const float* bih   = (const float*)d_in[11];
    const float* bhh   = (const float*)d_in[12];
    const float* lpw   = (const float*)d_in[13];
    const float* lpb   = (const float*)d_in[14];
    const float* ltw   = (const float*)d_in[15];
    const float* ltb   = (const float*)d_in[16];
    const float* liw   = (const float*)d_in[17];
    const float* lib   = (const float*)d_in[18];
    const float* rw1   = (const float*)d_in[19];
    const float* rb1   = (const float*)d_in[20];
    const float* rw2   = (const float*)d_in[21];
    const float* rb2   = (const float*)d_in[22];
    const float* cw1   = (const float*)d_in[23];
    const float* cb1   = (const float*)d_in[24];
    const float* cw2   = (const float*)d_in[25];
    const float* cb2   = (const float*)d_in[26];
    float* out = (float*)d_out;
    const int* srcp = ei;
    const int* dstp = ei + Ee;

    float *p_h1, *p_pos, *p_dinv, *p_txt, *p_nrm;
    __half *p_xwh, *p_E2h, *p_preh;
    unsigned* p_w1p;
    int *p_cnt, *p_off, *p_cur, *p_nbr;
    cudaGetSymbolAddress((void**)&p_xwh, g_xwh);
    cudaGetSymbolAddress((void**)&p_h1, g_h1);
    cudaGetSymbolAddress((void**)&p_pos, g_pos);
    cudaGetSymbolAddress((void**)&p_dinv, g_dinv);
    cudaGetSymbolAddress((void**)&p_cnt, g_cnt);
    cudaGetSymbolAddress((void**)&p_off, g_off);
    cudaGetSymbolAddress((void**)&p_cur, g_cur);
    cudaGetSymbolAddress((void**)&p_nbr, g_nbr);
    cudaGetSymbolAddress((void**)&p_nrm, g_nrm);
    cudaGetSymbolAddress((void**)&p_E2h, g_E2h);
    cudaGetSymbolAddress((void**)&p_txt, g_txt);
    cudaGetSymbolAddress((void**)&p_preh, g_preh);
    cudaGetSymbolAddress((void**)&p_w1p, g_w1p);

    static cudaStream_t sB = 0, sC = 0;
    static cudaEvent_t ev0 = 0, evB = 0, evC = 0, evX = 0;
    if (!sB) {
        cudaStreamCreateWithFlags(&sB, cudaStreamNonBlocking);
        cudaStreamCreateWithFlags(&sC, cudaStreamNonBlocking);
        cudaEventCreateWithFlags(&ev0, cudaEventDisableTiming);
        cudaEventCreateWithFlags(&evB, cudaEventDisableTiming);
        cudaEventCreateWithFlags(&evC, cudaEventDisableTiming);
        cudaEventCreateWithFlags(&evX, cudaEventDisableTiming);
        cudaFuncSetAttribute(k_gru_fused, cudaFuncAttributeMaxDynamicSharedMemorySize, GRU_SMEM);
        cudaFuncSetAttribute(k_edge_heads_f16, cudaFuncAttributeMaxDynamicSharedMemorySize, EH_SMEM);
    }

    // fork
    cudaEventRecord(ev0, 0);
    cudaStreamWaitEvent(sB, ev0, 0);
    cudaStreamWaitEvent(sC, ev0, 0);

    // ---- stream B: text chain ----
    {
        dim3 g((Vv + 63) / 64, H3 / 128);
        gemm_tf32<true, true><<<g, 256, 0, sB>>>(emb, Tt, wih, Tt, p_E2h, H3, Vv, H3, Tt);
        k_gru_fused<<<Nn / 32, 256, GRU_SMEM, sB>>>(xtext, p_E2h, whh, bih, bhh, p_txt);
        dim3 gd((Nn + 63) / 64, 2);
        gemm_tf32_dual<<<gd, 256, 0, sB>>>(p_txt, 128, ltw, ltw + 128 * 128, 128,
                                           p_preh + 256, 768, Nn, 128);
        cudaEventRecord(evB, sB);
    }

    // ---- stream C: xw1 (fp16), W1 pack, img pre pair ----
    {
        k_xw1<<<Nn, 128, 0, sC>>>(x, c1w, p_xwh);
        cudaEventRecord(evX, sC);
        k_packw<<<(2 * 3 * 64 * 128 + 255) / 256, 256, 0, sC>>>(rw1, cw1, p_w1p);
        dim3 gd((Nn + 63) / 64, 2);
        gemm_tf32_dual<<<gd, 256, 0, sC>>>(img, 256, liw, liw + 256 * 128, 128,
                                           p_preh + 512, 768, Nn, 256);
        cudaEventRecord(evC, sC);
    }

    // ---- default stream: CSR build || xw1, GCN gathers (fp16 operand), pos pre pair ----
    cudaMemsetAsync(p_cnt, 0, Nn * sizeof(int));
    cudaMemsetAsync(p_cur, 0, Nn * sizeof(int));
    k_hist<<<(Ee + 255) / 256, 256>>>(dstp, p_cnt);
    k_scan<<<1, 1024>>>(p_cnt, p_off, p_dinv);
    k_fill<<<(Ee + 255) / 256, 256>>>(srcp, dstp, p_dinv, p_off, p_cur, p_nbr, p_nrm);

    cudaStreamWaitEvent(0, evX, 0);
    k_gather<<<Nn / 8, 256>>>(p_xwh, p_nbr, p_nrm, p_off, p_dinv, c1b, p_h1);

    {
        dim3 g((Nn + 63) / 64, 1);
        gemm_tf32<false, true><<<g, 256>>>(p_h1, 128, c2w, 128, p_xwh, 128, Nn, 128, 128);
    }
    k_gather<<<Nn / 8, 256>>>(p_xwh, p_nbr, p_nrm, p_off, p_dinv, c2b, p_pos);

    {
        dim3 gd((Nn + 63) / 64, 2);
        gemm_tf32_dual<<<gd, 256>>>(p_pos, 128, lpw, lpw + 128 * 128, 128,
                                    p_preh + 0, 768, Nn, 128);
    }

    // join
    cudaStreamWaitEvent(0, evB, 0);
    cudaStreamWaitEvent(0, evC, 0);

    // fused edge heads
    k_edge_heads_f16<<<Ee / 64, 256, EH_SMEM>>>(srcp, dstp, p_preh, p_w1p,
                                                lpb, ltb, lib,
                                                rb1, rw2, rb2, cb1, cw2, cb2, out);
    (void)in_sizes; (void)n_in; (void)out_size;
}